// round 1
// baseline (speedup 1.0000x reference)
#include <cuda_runtime.h>
#include <math.h>

// ---------------------------------------------------------------------------
// EnhancedXLSTM  — round 1: correct fp32 implementation
//   B=16384, D=512, S=3, H=8, HD=64
// Pipeline:
//   1. xs[s]    = x @ Wt[s]^T + bt[s]                      (GEMM, z=S)
//   2. xs[s]    = gelu(layernorm(xs[s]))                    (rowwise kernel)
//   3. gates[s] = xs[s]@W_ih[s]^T + b_ih + h_prev[s]@W_hh[s]^T + b_hh (2 GEMMs)
//   4. LSTM pointwise -> h_new, c_new (directly into d_out)
//   5. q = ssm@Wq^T+bq ; k[s]=h_new[s]@Wk^T+bk ; v[s]=h_new[s]@Wv^T+bv
//   6. attention over S=3 -> fused
//   7. out = fused@out_proj^T + out_proj_b + sum_s h_new[s]@mix_w[:,sD:sD+D]^T + mix_b
// ---------------------------------------------------------------------------

namespace cfg {
constexpr int B  = 16384;
constexpr int D  = 512;
constexpr int S  = 3;
constexpr int H  = 8;
constexpr int HD = 64;

constexpr long long XS_OFF    = 0;
constexpr long long GATES_OFF = XS_OFF    + (long long)S * B * D;         // 25,165,824
constexpr long long Q_OFF     = GATES_OFF + (long long)S * B * 4 * D;     // +100,663,296
constexpr long long K_OFF     = Q_OFF     + (long long)B * D;
constexpr long long V_OFF     = K_OFF     + (long long)S * B * D;
constexpr long long FUSED_OFF = V_OFF     + (long long)S * B * D;
constexpr long long SCRATCH_TOTAL = FUSED_OFF + (long long)B * D;
}

// Scratch: ~736 MB of __device__ global memory (allowed; no runtime alloc).
__device__ float g_scratch[cfg::SCRATCH_TOTAL];

// ---------------------------------------------------------------------------
// SGEMM:  C[M,N] (+)= A[M,K] @ W[N,K]^T (+ bias[N])
//   A row-major ld=K, W row-major ld=ldw, C row-major ld=N.
//   z-batched via strides. All dims multiples of tile sizes (asserted).
// ---------------------------------------------------------------------------
namespace cfg {
constexpr int BM = 128, BN = 128, BK = 8, TM = 8, TN = 8;
constexpr int GEMM_THREADS = (BM / TM) * (BN / TN);   // 256
}

template <bool ACC, bool BIAS>
__global__ __launch_bounds__(cfg::GEMM_THREADS)
void sgemm_kernel(const float* __restrict__ A, long long strideA,
                  const float* __restrict__ W, long long strideW, int ldw,
                  const float* __restrict__ bias, long long strideBias,
                  float* __restrict__ C, long long strideC,
                  int N, int K)
{
    using namespace cfg;
    __shared__ float As[BK][BM];
    __shared__ float Ws[BK][BN];

    const int z = blockIdx.z;
    A += z * strideA;
    W += z * strideW;
    C += z * strideC;
    if (BIAS) bias += z * strideBias;

    const int rowBlock = blockIdx.y * BM;
    const int colBlock = blockIdx.x * BN;
    const int tid  = threadIdx.x;

    // Loader mapping: 256 threads, each loads one float4 per tile per matrix.
    const int lRow  = tid >> 1;          // 0..127
    const int lCol4 = (tid & 1) * 4;     // 0 or 4

    const float* Aptr = A + (size_t)(rowBlock + lRow) * K   + lCol4;
    const float* Wptr = W + (size_t)(colBlock + lRow) * ldw + lCol4;

    // Compute mapping
    const int ty = tid >> 4;             // 0..15  -> rows ty*8..ty*8+7
    const int tx = tid & 15;             // 0..15  -> cols tx*8..tx*8+7

    float acc[TM][TN];
#pragma unroll
    for (int i = 0; i < TM; i++)
#pragma unroll
        for (int j = 0; j < TN; j++) acc[i][j] = 0.0f;

    for (int k0 = 0; k0 < K; k0 += BK) {
        float4 av = *reinterpret_cast<const float4*>(Aptr + k0);
        float4 wv = *reinterpret_cast<const float4*>(Wptr + k0);
        As[lCol4 + 0][lRow] = av.x;
        As[lCol4 + 1][lRow] = av.y;
        As[lCol4 + 2][lRow] = av.z;
        As[lCol4 + 3][lRow] = av.w;
        Ws[lCol4 + 0][lRow] = wv.x;
        Ws[lCol4 + 1][lRow] = wv.y;
        Ws[lCol4 + 2][lRow] = wv.z;
        Ws[lCol4 + 3][lRow] = wv.w;
        __syncthreads();

#pragma unroll
        for (int k = 0; k < BK; k++) {
            float ra[TM], rw[TN];
            *reinterpret_cast<float4*>(&ra[0]) = *reinterpret_cast<const float4*>(&As[k][ty * TM]);
            *reinterpret_cast<float4*>(&ra[4]) = *reinterpret_cast<const float4*>(&As[k][ty * TM + 4]);
            *reinterpret_cast<float4*>(&rw[0]) = *reinterpret_cast<const float4*>(&Ws[k][tx * TN]);
            *reinterpret_cast<float4*>(&rw[4]) = *reinterpret_cast<const float4*>(&Ws[k][tx * TN + 4]);
#pragma unroll
            for (int i = 0; i < TM; i++)
#pragma unroll
                for (int j = 0; j < TN; j++)
                    acc[i][j] = fmaf(ra[i], rw[j], acc[i][j]);
        }
        __syncthreads();
    }

    // Epilogue
#pragma unroll
    for (int i = 0; i < TM; i++) {
        const int r = rowBlock + ty * TM + i;
        float* crow = C + (size_t)r * N + colBlock + tx * TN;
#pragma unroll
        for (int j = 0; j < TN; j++) {
            float v = acc[i][j];
            if (BIAS) v += bias[colBlock + tx * TN + j];
            if (ACC)  v += crow[j];
            crow[j] = v;
        }
    }
}

// ---------------------------------------------------------------------------
// Rowwise LayerNorm + exact GELU, in place. One 128-thread block per row of D=512.
// ---------------------------------------------------------------------------
__global__ __launch_bounds__(128)
void ln_gelu_kernel(float* __restrict__ xs,
                    const float* __restrict__ ln_g,
                    const float* __restrict__ ln_b)
{
    using namespace cfg;
    __shared__ float shm[4];
    const long long row = blockIdx.x;           // s*B + b
    const int s = (int)(row / B);
    float* p = xs + row * D;
    const int t = threadIdx.x;                  // 128 threads * 4 = 512

    float4 v = reinterpret_cast<float4*>(p)[t];

    float sum = v.x + v.y + v.z + v.w;
#pragma unroll
    for (int o = 16; o; o >>= 1) sum += __shfl_xor_sync(0xffffffffu, sum, o);
    if ((t & 31) == 0) shm[t >> 5] = sum;
    __syncthreads();
    const float mean = (shm[0] + shm[1] + shm[2] + shm[3]) * (1.0f / D);
    __syncthreads();

    const float dx = v.x - mean, dy = v.y - mean, dz = v.z - mean, dw = v.w - mean;
    float ss = dx * dx + dy * dy + dz * dz + dw * dw;
#pragma unroll
    for (int o = 16; o; o >>= 1) ss += __shfl_xor_sync(0xffffffffu, ss, o);
    if ((t & 31) == 0) shm[t >> 5] = ss;
    __syncthreads();
    const float var = (shm[0] + shm[1] + shm[2] + shm[3]) * (1.0f / D);
    const float inv = rsqrtf(var + 1e-5f);

    const float4 g4 = reinterpret_cast<const float4*>(ln_g + (long long)s * D)[t];
    const float4 b4 = reinterpret_cast<const float4*>(ln_b + (long long)s * D)[t];

    const float kInvSqrt2 = 0.70710678118654752f;
    float4 o4;
    float y;
    y = dx * inv * g4.x + b4.x; o4.x = 0.5f * y * (1.0f + erff(y * kInvSqrt2));
    y = dy * inv * g4.y + b4.y; o4.y = 0.5f * y * (1.0f + erff(y * kInvSqrt2));
    y = dz * inv * g4.z + b4.z; o4.z = 0.5f * y * (1.0f + erff(y * kInvSqrt2));
    y = dw * inv * g4.w + b4.w; o4.w = 0.5f * y * (1.0f + erff(y * kInvSqrt2));
    reinterpret_cast<float4*>(p)[t] = o4;
}

// ---------------------------------------------------------------------------
// LSTM pointwise: gates -> h_new, c_new
// ---------------------------------------------------------------------------
__device__ __forceinline__ float sigmoidf_(float x) { return 1.0f / (1.0f + expf(-x)); }

__global__ __launch_bounds__(256)
void lstm_kernel(const float* __restrict__ gates,
                 const float* __restrict__ c_prev,
                 const float* __restrict__ decays,
                 float* __restrict__ h_new,
                 float* __restrict__ c_new)
{
    using namespace cfg;
    const long long idx = (long long)blockIdx.x * blockDim.x + threadIdx.x;
    const long long total = (long long)S * B * D;
    if (idx >= total) return;

    const int d = (int)(idx % D);
    const long long bs = idx / D;
    const int b = (int)(bs % B);
    const int s = (int)(bs / B);

    const float* g = gates + ((long long)s * B + b) * (4 * D) + d;
    const float ig = g[0];
    const float fg = g[D];
    const float gg = g[2 * D];
    const float og = g[3 * D];

    const float cp    = c_prev[idx];
    const float c_l   = sigmoidf_(fg) * cp + sigmoidf_(ig) * tanhf(gg);
    const float h     = sigmoidf_(og) * tanhf(c_l);
    const float dd    = decays[s];

    h_new[idx] = h;
    c_new[idx] = dd * cp + (1.0f - dd) * c_l;
}

// ---------------------------------------------------------------------------
// Attention over S=3: one warp per (b, h). HD=64 -> 2 elems per lane.
// ---------------------------------------------------------------------------
__global__ __launch_bounds__(256)
void attn_kernel(const float* __restrict__ q,
                 const float* __restrict__ k,
                 const float* __restrict__ v,
                 float* __restrict__ fused)
{
    using namespace cfg;
    const int gwarp = (int)((blockIdx.x * (long long)blockDim.x + threadIdx.x) >> 5);
    const int lane  = threadIdx.x & 31;
    if (gwarp >= B * H) return;
    const int h = gwarp % H;
    const int b = gwarp / H;

    const float* qp = q + (long long)b * D + h * HD;
    const float q0 = qp[lane];
    const float q1 = qp[lane + 32];

    float logits[S];
#pragma unroll
    for (int s = 0; s < S; s++) {
        const float* kp = k + ((long long)s * B + b) * D + h * HD;
        float dot = q0 * kp[lane] + q1 * kp[lane + 32];
#pragma unroll
        for (int o = 16; o; o >>= 1) dot += __shfl_xor_sync(0xffffffffu, dot, o);
        logits[s] = dot * 0.125f;   // 1/sqrt(64)
    }
    float mx = fmaxf(logits[0], fmaxf(logits[1], logits[2]));
    float e0 = expf(logits[0] - mx);
    float e1 = expf(logits[1] - mx);
    float e2 = expf(logits[2] - mx);
    const float rs = 1.0f / (e0 + e1 + e2);
    e0 *= rs; e1 *= rs; e2 *= rs;

    float o0 = 0.0f, o1 = 0.0f;
    const float w[S] = {e0, e1, e2};
#pragma unroll
    for (int s = 0; s < S; s++) {
        const float* vp = v + ((long long)s * B + b) * D + h * HD;
        o0 = fmaf(w[s], vp[lane],      o0);
        o1 = fmaf(w[s], vp[lane + 32], o1);
    }
    float* fp = fused + (long long)b * D + h * HD;
    fp[lane]      = o0;
    fp[lane + 32] = o1;
}

// ---------------------------------------------------------------------------
// Launcher
// ---------------------------------------------------------------------------
extern "C" void kernel_launch(void* const* d_in, const int* in_sizes, int n_in,
                              void* d_out, int out_size)
{
    using namespace cfg;
    const float* x          = (const float*)d_in[0];
    const float* h_prev     = (const float*)d_in[1];
    const float* c_prev     = (const float*)d_in[2];
    const float* ssm_state  = (const float*)d_in[3];
    const float* Wt         = (const float*)d_in[4];
    const float* bt         = (const float*)d_in[5];
    const float* ln_g       = (const float*)d_in[6];
    const float* ln_b       = (const float*)d_in[7];
    const float* W_ih       = (const float*)d_in[8];
    const float* W_hh       = (const float*)d_in[9];
    const float* b_ih       = (const float*)d_in[10];
    const float* b_hh       = (const float*)d_in[11];
    const float* decays     = (const float*)d_in[12];
    const float* in_proj_w  = (const float*)d_in[13];
    const float* in_proj_b  = (const float*)d_in[14];
    const float* out_proj_w = (const float*)d_in[15];
    const float* out_proj_b = (const float*)d_in[16];
    const float* mix_w      = (const float*)d_in[17];
    const float* mix_b      = (const float*)d_in[18];

    float* out   = (float*)d_out;                       // (B, D)
    float* h_new = out + (long long)B * D;              // (S, B, D)
    float* c_new = h_new + (long long)S * B * D;        // (S, B, D)

    float* scratch = nullptr;
    cudaGetSymbolAddress((void**)&scratch, g_scratch);
    float* xs    = scratch + XS_OFF;
    float* gates = scratch + GATES_OFF;
    float* qb    = scratch + Q_OFF;
    float* kb    = scratch + K_OFF;
    float* vb    = scratch + V_OFF;
    float* fb    = scratch + FUSED_OFF;

    const dim3 blk(GEMM_THREADS);
    const dim3 gridD (D / BN,      B / BM, S);   // N=512, z=S
    const dim3 gridG (4 * D / BN,  B / BM, S);   // N=2048, z=S
    const dim3 grid1 (D / BN,      B / BM, 1);   // N=512, z=1

    // 1. xs[s] = x @ Wt[s]^T + bt[s]
    sgemm_kernel<false, true><<<gridD, blk>>>(
        x, 0, Wt, (long long)D * D, D, bt, D,
        xs, (long long)B * D, D, D);

    // 2. LN + GELU in place
    ln_gelu_kernel<<<S * B, 128>>>(xs, ln_g, ln_b);

    // 3. gates = xs@W_ih^T + b_ih   then  += h_prev@W_hh^T + b_hh
    sgemm_kernel<false, true><<<gridG, blk>>>(
        xs, (long long)B * D, W_ih, (long long)4 * D * D, D, b_ih, 4 * D,
        gates, (long long)B * 4 * D, 4 * D, D);
    sgemm_kernel<true, true><<<gridG, blk>>>(
        h_prev, (long long)B * D, W_hh, (long long)4 * D * D, D, b_hh, 4 * D,
        gates, (long long)B * 4 * D, 4 * D, D);

    // 4. LSTM pointwise -> h_new, c_new (into d_out)
    {
        const long long total = (long long)S * B * D;
        const int nb = (int)((total + 255) / 256);
        lstm_kernel<<<nb, 256>>>(gates, c_prev, decays, h_new, c_new);
    }

    // 5. q / k / v
    sgemm_kernel<false, true><<<grid1, blk>>>(
        ssm_state, 0, in_proj_w, 0, D, in_proj_b, 0,
        qb, 0, D, D);
    sgemm_kernel<false, true><<<gridD, blk>>>(
        h_new, (long long)B * D, in_proj_w + (long long)D * D, 0, D, in_proj_b + D, 0,
        kb, (long long)B * D, D, D);
    sgemm_kernel<false, true><<<gridD, blk>>>(
        h_new, (long long)B * D, in_proj_w + 2LL * D * D, 0, D, in_proj_b + 2 * D, 0,
        vb, (long long)B * D, D, D);

    // 6. attention -> fused
    attn_kernel<<<(B * H) / 8, 256>>>(qb, kb, vb, fb);

    // 7. out = fused@out_proj^T + out_proj_b  + sum_s h_new[s] @ mix_w[:, sD:(s+1)D]^T + mix_b
    sgemm_kernel<false, true><<<grid1, blk>>>(
        fb, 0, out_proj_w, 0, D, out_proj_b, 0,
        out, 0, D, D);
    sgemm_kernel<true, true><<<grid1, blk>>>(
        h_new, 0, mix_w, 0, S * D, mix_b, 0,
        out, 0, D, D);
    sgemm_kernel<true, false><<<grid1, blk>>>(
        h_new + (long long)B * D, 0, mix_w + D, 0, S * D, nullptr, 0,
        out, 0, D, D);
    sgemm_kernel<true, false><<<grid1, blk>>>(
        h_new + 2LL * B * D, 0, mix_w + 2 * D, 0, S * D, nullptr, 0,
        out, 0, D, D);
}

// round 3
// speedup vs baseline: 2.2122x; 2.2122x over previous
#include <cuda_runtime.h>
#include <cuda_bf16.h>
#include <cstdint>
#include <math.h>

// ---------------------------------------------------------------------------
// EnhancedXLSTM — round 3: mma.sync bf16 (3-term split) GEMMs
//   (tcgen05 unavailable: harness lowers via compute_103 virtual arch)
//   B=16384, D=512, S=3, H=8, HD=64
// ---------------------------------------------------------------------------

namespace cfg {
constexpr int B  = 16384;
constexpr int D  = 512;
constexpr int S  = 3;
constexpr int H  = 8;
constexpr int HD = 64;

constexpr long long N_BD  = (long long)B * D;          // 8,388,608
constexpr long long N_SBD = (long long)S * B * D;      // 25,165,824

// fp32 scratch
constexpr long long XS_OFF     = 0;
constexpr long long GATES_OFF  = XS_OFF    + N_SBD;
constexpr long long QF_OFF     = GATES_OFF + (long long)S * B * 4 * D;
constexpr long long KF_OFF     = QF_OFF    + N_BD;
constexpr long long VF_OFF     = KF_OFF    + N_SBD;
// packed hi/lo (u32 per element) scratch
constexpr long long XC_OFF     = VF_OFF    + N_SBD;
constexpr long long HPREVC_OFF = XC_OFF    + N_BD;
constexpr long long XSC_OFF    = HPREVC_OFF + N_SBD;
constexpr long long HNEWC_OFF  = XSC_OFF   + N_SBD;
constexpr long long SSMC_OFF   = HNEWC_OFF + N_SBD;
constexpr long long FBC_OFF    = SSMC_OFF  + N_BD;
constexpr long long WTC_OFF    = FBC_OFF   + N_BD;
constexpr long long WIHC_OFF   = WTC_OFF   + (long long)S * D * D;
constexpr long long WHHC_OFF   = WIHC_OFF  + (long long)S * 4 * D * D;
constexpr long long INPROJC_OFF= WHHC_OFF  + (long long)S * 4 * D * D;
constexpr long long OUTPROJC_OFF = INPROJC_OFF + (long long)3 * D * D;
constexpr long long MIXC_OFF   = OUTPROJC_OFF + (long long)D * D;
constexpr long long SCRATCH_TOTAL = MIXC_OFF + (long long)D * 3 * D;
}

__device__ float g_scratch[cfg::SCRATCH_TOTAL];

// ---------------------------------------------------------------------------
// bf16 hi/lo packing:  u32 = (hi16 << 16) | lo16
//   hi = truncate-to-bf16(f) (top 16 bits), lo = round-to-bf16(f - hi)
// ---------------------------------------------------------------------------
__device__ __forceinline__ uint32_t split_combine(float f) {
    uint32_t u  = __float_as_uint(f);
    uint32_t hi = u & 0xffff0000u;
    float r = f - __uint_as_float(hi);
    uint16_t lo = __bfloat16_as_ushort(__float2bfloat16(r));
    return hi | (uint32_t)lo;
}

__global__ __launch_bounds__(256)
void convert_kernel(const float4* __restrict__ src, uint4* __restrict__ dst, long long n4)
{
    const long long i = (long long)blockIdx.x * blockDim.x + threadIdx.x;
    if (i >= n4) return;
    const float4 v = src[i];
    uint4 o;
    o.x = split_combine(v.x);
    o.y = split_combine(v.y);
    o.z = split_combine(v.z);
    o.w = split_combine(v.w);
    dst[i] = o;
}

// ---------------------------------------------------------------------------
// MMA helpers
// ---------------------------------------------------------------------------
__device__ __forceinline__ uint32_t smem_u32(const void* p) {
    uint32_t a;
    asm("{ .reg .u64 t; cvta.to.shared.u64 t, %1; cvt.u32.u64 %0, t; }" : "=r"(a) : "l"(p));
    return a;
}

#define LDSM_X4(r, addr) \
    asm volatile("ldmatrix.sync.aligned.m8n8.x4.shared.b16 {%0,%1,%2,%3}, [%4];" \
                 : "=r"((r)[0]), "=r"((r)[1]), "=r"((r)[2]), "=r"((r)[3]) : "r"(addr))

__device__ __forceinline__ void mma_bf16(float* c, const uint32_t* a, uint32_t b0, uint32_t b1) {
    asm volatile(
        "mma.sync.aligned.m16n8k16.row.col.f32.bf16.bf16.f32 "
        "{%0,%1,%2,%3}, {%4,%5,%6,%7}, {%8,%9}, {%0,%1,%2,%3};"
        : "+f"(c[0]), "+f"(c[1]), "+f"(c[2]), "+f"(c[3])
        : "r"(a[0]), "r"(a[1]), "r"(a[2]), "r"(a[3]), "r"(b0), "r"(b1));
}

__device__ __forceinline__ void sts_v2(uint32_t addr, uint32_t w0, uint32_t w1) {
    asm volatile("st.shared.v2.b32 [%0], {%1,%2};" :: "r"(addr), "r"(w0), "r"(w1) : "memory");
}

// ---------------------------------------------------------------------------
// GEMM:  C[z][M,N] = sum_seg A_seg[z][M,512] @ W_seg[z][N,512]^T + sum bias
//   A,W are packed u32 (hi|lo).  Tile 128x128, 256 thr, warp tile 64x32.
//   SMEM rows: 32 bf16 = 64B data, stride 80B (conflict-free ldmatrix).
// ---------------------------------------------------------------------------
struct SegC {
    const uint32_t* A; const uint32_t* W; const float* bias;
    long long sA, sW, sB;
    int ldA, ldW;
};
template <int NSEG> struct SegsC { SegC s[NSEG]; };

constexpr int ROW_STRIDE = 80;                 // bytes
constexpr int PIECE = 128 * ROW_STRIDE;        // 10240 B per matrix piece
constexpr int OFF_AH = 0, OFF_AL = PIECE, OFF_BH = 2 * PIECE, OFF_BL = 3 * PIECE;
constexpr int OFF_BIAS = 4 * PIECE;            // 40960
constexpr int SMEM_BYTES = OFF_BIAS + 512;     // 41472

template <int NSEG>
__global__ __launch_bounds__(256)
void mma_gemm_kernel(SegsC<NSEG> segs, float* __restrict__ C,
                     long long strideC, int ldC)
{
    __shared__ __align__(16) uint8_t buf[SMEM_BYTES];
    const uint32_t sb = smem_u32(buf);

    const int tid  = threadIdx.x;
    const int wid  = tid >> 5;
    const int lane = tid & 31;
    const int z = blockIdx.z;
    const int rowBlock = blockIdx.y * 128;
    const int colBlock = blockIdx.x * 128;

    // Bias sum for this column block
    if (tid < 128) {
        float acc = 0.0f;
#pragma unroll
        for (int sgi = 0; sgi < NSEG; ++sgi) {
            const SegC& sg = segs.s[sgi];
            if (sg.bias) acc += sg.bias[z * sg.sB + colBlock + tid];
        }
        reinterpret_cast<float*>(buf + OFF_BIAS)[tid] = acc;
    }

    // Loader mapping: thread -> (baseRow, kq); handles rows baseRow + 32*i
    const int baseRow = tid >> 3;     // 0..31
    const int kq      = tid & 7;      // quad of 4 elems within the 32-wide chunk
    uint32_t stsOff[4];
#pragma unroll
    for (int i = 0; i < 4; ++i)
        stsOff[i] = (uint32_t)((baseRow + i * 32) * ROW_STRIDE + kq * 8);

    // ldmatrix lane mapping
    const int warp_m = wid >> 2;      // 0..1
    const int warp_n = wid & 3;       // 0..3
    const int xrow    = (lane & 7) | (((lane >> 3) & 1) << 3);  // 0..15
    const int kb_lane = ((lane >> 4) & 1) * 16;
    uint32_t aOff[4], bOff[2];
#pragma unroll
    for (int mf = 0; mf < 4; ++mf)
        aOff[mf] = (uint32_t)((warp_m * 64 + mf * 16 + xrow) * ROW_STRIDE + kb_lane);
#pragma unroll
    for (int p = 0; p < 2; ++p)
        bOff[p] = (uint32_t)((warp_n * 32 + p * 16 + xrow) * ROW_STRIDE + kb_lane);

    float acc[4][4][4];
#pragma unroll
    for (int mf = 0; mf < 4; ++mf)
#pragma unroll
        for (int nf = 0; nf < 4; ++nf)
#pragma unroll
            for (int e = 0; e < 4; ++e) acc[mf][nf][e] = 0.0f;

    uint4 sa[4], sw[4];

    auto ldg_chunk = [&](int t) {
        const int sgi = t >> 4;
        const int kc  = t & 15;
        const SegC& sg = segs.s[sgi];
        const uint32_t* Ab = sg.A + (long long)z * sg.sA
                           + (size_t)(rowBlock + baseRow) * sg.ldA + kc * 32 + kq * 4;
        const uint32_t* Wb = sg.W + (long long)z * sg.sW
                           + (size_t)(colBlock + baseRow) * sg.ldW + kc * 32 + kq * 4;
#pragma unroll
        for (int i = 0; i < 4; ++i) {
            sa[i] = *reinterpret_cast<const uint4*>(Ab + (size_t)i * 32 * sg.ldA);
            sw[i] = *reinterpret_cast<const uint4*>(Wb + (size_t)i * 32 * sg.ldW);
        }
    };

    auto sts_chunk = [&]() {
#pragma unroll
        for (int i = 0; i < 4; ++i) {
            uint32_t h0 = __byte_perm(sa[i].x, sa[i].y, 0x7632);
            uint32_t l0 = __byte_perm(sa[i].x, sa[i].y, 0x5410);
            uint32_t h1 = __byte_perm(sa[i].z, sa[i].w, 0x7632);
            uint32_t l1 = __byte_perm(sa[i].z, sa[i].w, 0x5410);
            sts_v2(sb + OFF_AH + stsOff[i], h0, h1);
            sts_v2(sb + OFF_AL + stsOff[i], l0, l1);
            h0 = __byte_perm(sw[i].x, sw[i].y, 0x7632);
            l0 = __byte_perm(sw[i].x, sw[i].y, 0x5410);
            h1 = __byte_perm(sw[i].z, sw[i].w, 0x7632);
            l1 = __byte_perm(sw[i].z, sw[i].w, 0x5410);
            sts_v2(sb + OFF_BH + stsOff[i], h0, h1);
            sts_v2(sb + OFF_BL + stsOff[i], l0, l1);
        }
    };

    const int T = NSEG * 16;
    ldg_chunk(0);
    sts_chunk();
    __syncthreads();

#pragma unroll 1
    for (int t = 0; t < T; ++t) {
        const bool hasNext = (t + 1 < T);
        if (hasNext) ldg_chunk(t + 1);

        // compute on smem chunk t
#pragma unroll
        for (int h = 0; h < 2; ++h) {
            const uint32_t hb = h * 32;
            uint32_t Ah[4][4], Al[4][4], Bh[2][4], Bl[2][4];
#pragma unroll
            for (int mf = 0; mf < 4; ++mf) {
                LDSM_X4(Ah[mf], sb + OFF_AH + aOff[mf] + hb);
                LDSM_X4(Al[mf], sb + OFF_AL + aOff[mf] + hb);
            }
#pragma unroll
            for (int p = 0; p < 2; ++p) {
                LDSM_X4(Bh[p], sb + OFF_BH + bOff[p] + hb);
                LDSM_X4(Bl[p], sb + OFF_BL + bOff[p] + hb);
            }
#pragma unroll
            for (int mf = 0; mf < 4; ++mf)
#pragma unroll
                for (int nf = 0; nf < 4; ++nf) {
                    const int p = nf >> 1, s = nf & 1;
                    mma_bf16(acc[mf][nf], Ah[mf], Bh[p][s], Bh[p][s + 2]);
                    mma_bf16(acc[mf][nf], Ah[mf], Bl[p][s], Bl[p][s + 2]);
                    mma_bf16(acc[mf][nf], Al[mf], Bh[p][s], Bh[p][s + 2]);
                }
        }
        __syncthreads();
        if (hasNext) {
            sts_chunk();
            __syncthreads();
        }
    }

    // Epilogue
    const float* biasS = reinterpret_cast<const float*>(buf + OFF_BIAS);
    float* Cb = C + (long long)z * strideC;
#pragma unroll
    for (int mf = 0; mf < 4; ++mf) {
#pragma unroll
        for (int nf = 0; nf < 4; ++nf) {
            const int lcol = warp_n * 32 + nf * 8 + (lane & 3) * 2;
            const int r0   = rowBlock + warp_m * 64 + mf * 16 + (lane >> 2);
            const float b0 = biasS[lcol], b1 = biasS[lcol + 1];
            float2 v0 = {acc[mf][nf][0] + b0, acc[mf][nf][1] + b1};
            float2 v1 = {acc[mf][nf][2] + b0, acc[mf][nf][3] + b1};
            *reinterpret_cast<float2*>(Cb + (size_t)r0 * ldC + colBlock + lcol) = v0;
            *reinterpret_cast<float2*>(Cb + (size_t)(r0 + 8) * ldC + colBlock + lcol) = v1;
        }
    }
}

// ---------------------------------------------------------------------------
// LayerNorm + exact GELU: reads fp32 xs, writes packed xs_c
// ---------------------------------------------------------------------------
__global__ __launch_bounds__(128)
void ln_gelu_kernel(const float* __restrict__ xs,
                    uint32_t* __restrict__ xs_c,
                    const float* __restrict__ ln_g,
                    const float* __restrict__ ln_b)
{
    using namespace cfg;
    __shared__ float shm[4];
    const long long row = blockIdx.x;
    const int s = (int)(row / B);
    const float* p = xs + row * D;
    const int t = threadIdx.x;

    float4 v = reinterpret_cast<const float4*>(p)[t];

    float sum = v.x + v.y + v.z + v.w;
#pragma unroll
    for (int o = 16; o; o >>= 1) sum += __shfl_xor_sync(0xffffffffu, sum, o);
    if ((t & 31) == 0) shm[t >> 5] = sum;
    __syncthreads();
    const float mean = (shm[0] + shm[1] + shm[2] + shm[3]) * (1.0f / D);
    __syncthreads();

    const float dx = v.x - mean, dy = v.y - mean, dz = v.z - mean, dw = v.w - mean;
    float ss = dx * dx + dy * dy + dz * dz + dw * dw;
#pragma unroll
    for (int o = 16; o; o >>= 1) ss += __shfl_xor_sync(0xffffffffu, ss, o);
    if ((t & 31) == 0) shm[t >> 5] = ss;
    __syncthreads();
    const float var = (shm[0] + shm[1] + shm[2] + shm[3]) * (1.0f / D);
    const float inv = rsqrtf(var + 1e-5f);

    const float4 g4 = reinterpret_cast<const float4*>(ln_g + (long long)s * D)[t];
    const float4 b4 = reinterpret_cast<const float4*>(ln_b + (long long)s * D)[t];

    const float kInvSqrt2 = 0.70710678118654752f;
    float y;
    uint4 o4;
    y = dx * inv * g4.x + b4.x; o4.x = split_combine(0.5f * y * (1.0f + erff(y * kInvSqrt2)));
    y = dy * inv * g4.y + b4.y; o4.y = split_combine(0.5f * y * (1.0f + erff(y * kInvSqrt2)));
    y = dz * inv * g4.z + b4.z; o4.z = split_combine(0.5f * y * (1.0f + erff(y * kInvSqrt2)));
    y = dw * inv * g4.w + b4.w; o4.w = split_combine(0.5f * y * (1.0f + erff(y * kInvSqrt2)));
    reinterpret_cast<uint4*>(xs_c + row * D)[t] = o4;
}

// ---------------------------------------------------------------------------
// LSTM pointwise: gates -> h_new (fp32 + packed), c_new
// ---------------------------------------------------------------------------
__device__ __forceinline__ float sigmoidf_(float x) { return 1.0f / (1.0f + expf(-x)); }

__global__ __launch_bounds__(256)
void lstm_kernel(const float* __restrict__ gates,
                 const float* __restrict__ c_prev,
                 const float* __restrict__ decays,
                 float* __restrict__ h_new,
                 uint32_t* __restrict__ hnew_c,
                 float* __restrict__ c_new)
{
    using namespace cfg;
    const long long idx = (long long)blockIdx.x * blockDim.x + threadIdx.x;
    const long long total = (long long)S * B * D;
    if (idx >= total) return;

    const int d = (int)(idx % D);
    const long long bs = idx / D;
    const int b = (int)(bs % B);
    const int s = (int)(bs / B);

    const float* g = gates + ((long long)s * B + b) * (4 * D) + d;
    const float ig = g[0];
    const float fg = g[D];
    const float gg = g[2 * D];
    const float og = g[3 * D];

    const float cp  = c_prev[idx];
    const float c_l = sigmoidf_(fg) * cp + sigmoidf_(ig) * tanhf(gg);
    const float h   = sigmoidf_(og) * tanhf(c_l);
    const float dd  = decays[s];

    h_new[idx]  = h;
    hnew_c[idx] = split_combine(h);
    c_new[idx]  = dd * cp + (1.0f - dd) * c_l;
}

// ---------------------------------------------------------------------------
// Attention over S=3: one warp per (b, h) -> packed fb_c
// ---------------------------------------------------------------------------
__global__ __launch_bounds__(256)
void attn_kernel(const float* __restrict__ q,
                 const float* __restrict__ k,
                 const float* __restrict__ v,
                 uint32_t* __restrict__ fused_c)
{
    using namespace cfg;
    const int gwarp = (int)((blockIdx.x * (long long)blockDim.x + threadIdx.x) >> 5);
    const int lane  = threadIdx.x & 31;
    if (gwarp >= B * H) return;
    const int h = gwarp % H;
    const int b = gwarp / H;

    const float* qp = q + (long long)b * D + h * HD;
    const float q0 = qp[lane];
    const float q1 = qp[lane + 32];

    float logits[S];
#pragma unroll
    for (int s = 0; s < S; s++) {
        const float* kp = k + ((long long)s * B + b) * D + h * HD;
        float dot = q0 * kp[lane] + q1 * kp[lane + 32];
#pragma unroll
        for (int o = 16; o; o >>= 1) dot += __shfl_xor_sync(0xffffffffu, dot, o);
        logits[s] = dot * 0.125f;
    }
    float mx = fmaxf(logits[0], fmaxf(logits[1], logits[2]));
    float e0 = expf(logits[0] - mx);
    float e1 = expf(logits[1] - mx);
    float e2 = expf(logits[2] - mx);
    const float rs = 1.0f / (e0 + e1 + e2);
    e0 *= rs; e1 *= rs; e2 *= rs;

    float o0 = 0.0f, o1 = 0.0f;
    const float w[S] = {e0, e1, e2};
#pragma unroll
    for (int s = 0; s < S; s++) {
        const float* vp = v + ((long long)s * B + b) * D + h * HD;
        o0 = fmaf(w[s], vp[lane],      o0);
        o1 = fmaf(w[s], vp[lane + 32], o1);
    }
    uint32_t* fp = fused_c + (long long)b * D + h * HD;
    fp[lane]      = split_combine(o0);
    fp[lane + 32] = split_combine(o1);
}

// ---------------------------------------------------------------------------
// Launcher
// ---------------------------------------------------------------------------
static inline void launch_convert(const float* src, uint32_t* dst, long long n)
{
    const long long n4 = n / 4;
    convert_kernel<<<(int)((n4 + 255) / 256), 256>>>(
        (const float4*)src, (uint4*)dst, n4);
}

extern "C" void kernel_launch(void* const* d_in, const int* in_sizes, int n_in,
                              void* d_out, int out_size)
{
    using namespace cfg;
    const float* x          = (const float*)d_in[0];
    const float* h_prev     = (const float*)d_in[1];
    const float* c_prev     = (const float*)d_in[2];
    const float* ssm_state  = (const float*)d_in[3];
    const float* Wt         = (const float*)d_in[4];
    const float* bt         = (const float*)d_in[5];
    const float* ln_g       = (const float*)d_in[6];
    const float* ln_b       = (const float*)d_in[7];
    const float* W_ih       = (const float*)d_in[8];
    const float* W_hh       = (const float*)d_in[9];
    const float* b_ih       = (const float*)d_in[10];
    const float* b_hh       = (const float*)d_in[11];
    const float* decays     = (const float*)d_in[12];
    const float* in_proj_w  = (const float*)d_in[13];
    const float* in_proj_b  = (const float*)d_in[14];
    const float* out_proj_w = (const float*)d_in[15];
    const float* out_proj_b = (const float*)d_in[16];
    const float* mix_w      = (const float*)d_in[17];
    const float* mix_b      = (const float*)d_in[18];

    float* out   = (float*)d_out;
    float* h_new = out + N_BD;
    float* c_new = h_new + N_SBD;

    float* scratch = nullptr;
    cudaGetSymbolAddress((void**)&scratch, g_scratch);
    float* xs       = scratch + XS_OFF;
    float* gates    = scratch + GATES_OFF;
    float* qf       = scratch + QF_OFF;
    float* kf       = scratch + KF_OFF;
    float* vf       = scratch + VF_OFF;
    uint32_t* x_c      = (uint32_t*)(scratch + XC_OFF);
    uint32_t* hprev_c  = (uint32_t*)(scratch + HPREVC_OFF);
    uint32_t* xs_c     = (uint32_t*)(scratch + XSC_OFF);
    uint32_t* hnew_c   = (uint32_t*)(scratch + HNEWC_OFF);
    uint32_t* ssm_c    = (uint32_t*)(scratch + SSMC_OFF);
    uint32_t* fb_c     = (uint32_t*)(scratch + FBC_OFF);
    uint32_t* Wt_c     = (uint32_t*)(scratch + WTC_OFF);
    uint32_t* Wih_c    = (uint32_t*)(scratch + WIHC_OFF);
    uint32_t* Whh_c    = (uint32_t*)(scratch + WHHC_OFF);
    uint32_t* inproj_c = (uint32_t*)(scratch + INPROJC_OFF);
    uint32_t* outproj_c= (uint32_t*)(scratch + OUTPROJC_OFF);
    uint32_t* mix_c    = (uint32_t*)(scratch + MIXC_OFF);

    // --- input/weight conversions (packed hi|lo) ---
    launch_convert(x,          x_c,       N_BD);
    launch_convert(h_prev,     hprev_c,   N_SBD);
    launch_convert(ssm_state,  ssm_c,     N_BD);
    launch_convert(Wt,         Wt_c,      (long long)S * D * D);
    launch_convert(W_ih,       Wih_c,     (long long)S * 4 * D * D);
    launch_convert(W_hh,       Whh_c,     (long long)S * 4 * D * D);
    launch_convert(in_proj_w,  inproj_c,  (long long)3 * D * D);
    launch_convert(out_proj_w, outproj_c, (long long)D * D);
    launch_convert(mix_w,      mix_c,     (long long)D * 3 * D);

    const dim3 blk(256);

    // 1. xs[s] = x @ Wt[s]^T + bt[s]
    {
        SegsC<1> sg;
        sg.s[0] = {x_c, Wt_c, bt, 0, (long long)D * D, D, D, D};
        mma_gemm_kernel<1><<<dim3(D / 128, B / 128, S), blk>>>(sg, xs, N_BD, D);
    }

    // 2. LN + GELU -> xs_c
    ln_gelu_kernel<<<S * B, 128>>>(xs, xs_c, ln_g, ln_b);

    // 3. gates = xs@W_ih^T + b_ih + h_prev@W_hh^T + b_hh (fused K=1024)
    {
        SegsC<2> sg;
        sg.s[0] = {xs_c,    Wih_c, b_ih, N_BD, (long long)4 * D * D, 4 * D, D, D};
        sg.s[1] = {hprev_c, Whh_c, b_hh, N_BD, (long long)4 * D * D, 4 * D, D, D};
        mma_gemm_kernel<2><<<dim3(4 * D / 128, B / 128, S), blk>>>(
            sg, gates, (long long)B * 4 * D, 4 * D);
    }

    // 4. LSTM pointwise -> h_new (fp32 + packed), c_new
    lstm_kernel<<<(int)((N_SBD + 255) / 256), 256>>>(
        gates, c_prev, decays, h_new, hnew_c, c_new);

    // 5. q / k / v
    {
        SegsC<1> sg;
        sg.s[0] = {ssm_c, inproj_c, in_proj_b, 0, 0, 0, D, D};
        mma_gemm_kernel<1><<<dim3(D / 128, B / 128, 1), blk>>>(sg, qf, 0, D);
    }
    {
        SegsC<1> sg;
        sg.s[0] = {hnew_c, inproj_c + (long long)D * D, in_proj_b + D, N_BD, 0, 0, D, D};
        mma_gemm_kernel<1><<<dim3(D / 128, B / 128, S), blk>>>(sg, kf, N_BD, D);
    }
    {
        SegsC<1> sg;
        sg.s[0] = {hnew_c, inproj_c + 2LL * D * D, in_proj_b + 2 * D, N_BD, 0, 0, D, D};
        mma_gemm_kernel<1><<<dim3(D / 128, B / 128, S), blk>>>(sg, vf, N_BD, D);
    }

    // 6. attention -> fb_c
    attn_kernel<<<(B * H) / 8, 256>>>(qf, kf, vf, fb_c);

    // 7. out = fused@out_proj^T + out_proj_b + sum_s h_new[s]@mix_w[:,sD:]^T + mix_b
    {
        SegsC<4> sg;
        sg.s[0] = {fb_c,               outproj_c,     out_proj_b, 0, 0, 0, D, D};
        sg.s[1] = {hnew_c,             mix_c,         mix_b,      0, 0, 0, D, S * D};
        sg.s[2] = {hnew_c + N_BD,      mix_c + D,     nullptr,    0, 0, 0, D, S * D};
        sg.s[3] = {hnew_c + 2 * N_BD,  mix_c + 2 * D, nullptr,    0, 0, 0, D, S * D};
        mma_gemm_kernel<4><<<dim3(D / 128, B / 128, 1), blk>>>(sg, out, 0, D);
    }
}

// round 4
// speedup vs baseline: 3.3771x; 1.5266x over previous
#include <cuda_runtime.h>
#include <cuda_fp16.h>
#include <cstdint>
#include <math.h>

// ---------------------------------------------------------------------------
// EnhancedXLSTM — round 4: mma.sync fp16, 2-term split (A fp16, W = hi+lo fp16),
// double-buffered smem GEMM pipeline.
//   B=16384, D=512, S=3, H=8, HD=64
// ---------------------------------------------------------------------------

namespace cfg {
constexpr int B  = 16384;
constexpr int D  = 512;
constexpr int S  = 3;
constexpr int H  = 8;
constexpr int HD = 64;

constexpr long long N_BD  = (long long)B * D;
constexpr long long N_SBD = (long long)S * B * D;

// fp32 scratch (float units)
constexpr long long XS_OFF     = 0;
constexpr long long GATES_OFF  = XS_OFF    + N_SBD;
constexpr long long QF_OFF     = GATES_OFF + 4 * N_SBD;
constexpr long long KF_OFF     = QF_OFF    + N_BD;
constexpr long long VF_OFF     = KF_OFF    + N_SBD;
// fp16 activation scratch (float units = halfs/2)
constexpr long long XH_OFF     = VF_OFF    + N_SBD;
constexpr long long HPREVH_OFF = XH_OFF    + N_BD / 2;
constexpr long long XSH_OFF    = HPREVH_OFF + N_SBD / 2;
constexpr long long HNEWH_OFF  = XSH_OFF   + N_SBD / 2;
constexpr long long SSMH_OFF   = HNEWH_OFF + N_SBD / 2;
constexpr long long FBH_OFF    = SSMH_OFF  + N_BD / 2;
// packed weight scratch (u32 = hi16|lo16 fp16, 1 float unit per elem)
constexpr long long WTP_OFF     = FBH_OFF  + N_BD / 2;
constexpr long long WIHP_OFF    = WTP_OFF  + (long long)S * D * D;
constexpr long long WHHP_OFF    = WIHP_OFF + (long long)S * 4 * D * D;
constexpr long long INPROJP_OFF = WHHP_OFF + (long long)S * 4 * D * D;
constexpr long long OUTPROJP_OFF= INPROJP_OFF + (long long)3 * D * D;
constexpr long long MIXP_OFF    = OUTPROJP_OFF + (long long)D * D;
constexpr long long SCRATCH_TOTAL = MIXP_OFF + (long long)D * 3 * D;
}

__device__ float g_scratch[cfg::SCRATCH_TOTAL];

// ---------------------------------------------------------------------------
// Conversion helpers
// ---------------------------------------------------------------------------
__device__ __forceinline__ uint32_t split_pack_f16(float f) {
    __half h = __float2half_rn(f);
    float r = f - __half2float(h);
    __half l = __float2half_rn(r);
    return ((uint32_t)__half_as_ushort(h) << 16) | (uint32_t)__half_as_ushort(l);
}
__device__ __forceinline__ uint2 pack_half4(float4 v) {
    __half2 p0 = __floats2half2_rn(v.x, v.y);
    __half2 p1 = __floats2half2_rn(v.z, v.w);
    uint2 o;
    o.x = *reinterpret_cast<uint32_t*>(&p0);
    o.y = *reinterpret_cast<uint32_t*>(&p1);
    return o;
}

struct CvtJob { const float4* src; void* dst; long long n4; };
template <int NJ> struct CvtJobs { CvtJob j[NJ]; };

// fp32 -> fp16 (activations)
template <int NJ>
__global__ __launch_bounds__(256)
void cvt_half_kernel(CvtJobs<NJ> jobs)
{
    long long i = (long long)blockIdx.x * blockDim.x + threadIdx.x;
#pragma unroll
    for (int jj = 0; jj < NJ; ++jj) {
        const CvtJob J = jobs.j[jj];
        if (i < J.n4) {
            ((uint2*)J.dst)[i] = pack_half4(J.src[i]);
            return;
        }
        i -= J.n4;
    }
}

// fp32 -> packed hi|lo fp16 (weights)
template <int NJ>
__global__ __launch_bounds__(256)
void cvt_pack_kernel(CvtJobs<NJ> jobs)
{
    long long i = (long long)blockIdx.x * blockDim.x + threadIdx.x;
#pragma unroll
    for (int jj = 0; jj < NJ; ++jj) {
        const CvtJob J = jobs.j[jj];
        if (i < J.n4) {
            const float4 v = J.src[i];
            uint4 o;
            o.x = split_pack_f16(v.x);
            o.y = split_pack_f16(v.y);
            o.z = split_pack_f16(v.z);
            o.w = split_pack_f16(v.w);
            ((uint4*)J.dst)[i] = o;
            return;
        }
        i -= J.n4;
    }
}

// ---------------------------------------------------------------------------
// MMA helpers
// ---------------------------------------------------------------------------
__device__ __forceinline__ uint32_t smem_u32(const void* p) {
    uint32_t a;
    asm("{ .reg .u64 t; cvta.to.shared.u64 t, %1; cvt.u32.u64 %0, t; }" : "=r"(a) : "l"(p));
    return a;
}

#define LDSM_X4(r, addr) \
    asm volatile("ldmatrix.sync.aligned.m8n8.x4.shared.b16 {%0,%1,%2,%3}, [%4];" \
                 : "=r"((r)[0]), "=r"((r)[1]), "=r"((r)[2]), "=r"((r)[3]) : "r"(addr))

__device__ __forceinline__ void mma_f16(float* c, const uint32_t* a, uint32_t b0, uint32_t b1) {
    asm volatile(
        "mma.sync.aligned.m16n8k16.row.col.f32.f16.f16.f32 "
        "{%0,%1,%2,%3}, {%4,%5,%6,%7}, {%8,%9}, {%0,%1,%2,%3};"
        : "+f"(c[0]), "+f"(c[1]), "+f"(c[2]), "+f"(c[3])
        : "r"(a[0]), "r"(a[1]), "r"(a[2]), "r"(a[3]), "r"(b0), "r"(b1));
}

__device__ __forceinline__ void sts_v2(uint32_t addr, uint32_t w0, uint32_t w1) {
    asm volatile("st.shared.v2.b32 [%0], {%1,%2};" :: "r"(addr), "r"(w0), "r"(w1) : "memory");
}

// ---------------------------------------------------------------------------
// GEMM:  C[z][M,N] = sum_seg A_seg[z][M,512] @ W_seg[z][N,512]^T + sum bias
//   A: fp16 (__half). W: packed u32 (hi|lo fp16). Tile 128x128, 256 thr,
//   warp tile 64x32, K-chunk 32, double-buffered smem, 2 MMAs per position.
// ---------------------------------------------------------------------------
struct SegH {
    const __half* A; const uint32_t* W; const float* bias;
    long long sA, sW, sB;
    int ldA, ldW;
};
template <int NSEG> struct SegsH { SegH s[NSEG]; };

constexpr int ROW_STRIDE = 80;               // bytes per 128-row piece row
constexpr int PIECE = 128 * ROW_STRIDE;      // 10240
constexpr int STAGE = 3 * PIECE;             // A, BH, BL
constexpr int OFF_BIAS = 2 * STAGE;          // 61440
constexpr int SMEM_BYTES = OFF_BIAS + 512;   // 61952

template <int NSEG>
__global__ __launch_bounds__(256, 1)
void mma_gemm_kernel(SegsH<NSEG> segs, float* __restrict__ C,
                     long long strideC, int ldC)
{
    extern __shared__ __align__(16) uint8_t buf[];
    const uint32_t sb = smem_u32(buf);

    const int tid  = threadIdx.x;
    const int wid  = tid >> 5;
    const int lane = tid & 31;
    const int z = blockIdx.z;
    const int rowBlock = blockIdx.y * 128;
    const int colBlock = blockIdx.x * 128;

    // Bias sum for this column block
    if (tid < 128) {
        float acc = 0.0f;
#pragma unroll
        for (int sgi = 0; sgi < NSEG; ++sgi) {
            const SegH& sg = segs.s[sgi];
            if (sg.bias) acc += sg.bias[z * sg.sB + colBlock + tid];
        }
        reinterpret_cast<float*>(buf + OFF_BIAS)[tid] = acc;
    }

    // Loader mapping
    const int baseRow = tid >> 3;     // 0..31, handles rows baseRow + 32*i
    const int kq      = tid & 7;      // 4-elem quad within 32-wide K chunk
    uint32_t stsOff[4];
#pragma unroll
    for (int i = 0; i < 4; ++i)
        stsOff[i] = (uint32_t)((baseRow + i * 32) * ROW_STRIDE + kq * 8);

    // ldmatrix mapping
    const int warp_m = wid >> 2;
    const int warp_n = wid & 3;
    const int xrow    = (lane & 7) | (((lane >> 3) & 1) << 3);
    const int kb_lane = ((lane >> 4) & 1) * 16;
    uint32_t aOff[4], bOff[2];
#pragma unroll
    for (int mf = 0; mf < 4; ++mf)
        aOff[mf] = (uint32_t)((warp_m * 64 + mf * 16 + xrow) * ROW_STRIDE + kb_lane);
#pragma unroll
    for (int p = 0; p < 2; ++p)
        bOff[p] = (uint32_t)((warp_n * 32 + p * 16 + xrow) * ROW_STRIDE + kb_lane);

    float acc[4][4][4];
#pragma unroll
    for (int mf = 0; mf < 4; ++mf)
#pragma unroll
        for (int nf = 0; nf < 4; ++nf)
#pragma unroll
            for (int e = 0; e < 4; ++e) acc[mf][nf][e] = 0.0f;

    uint2 sa[4];
    uint4 sw[4];

    auto ldg_chunk = [&](int t) {
        const int sgi = t >> 4;
        const int kc  = t & 15;
        const SegH& sg = segs.s[sgi];
        const __half* Ab = sg.A + (long long)z * sg.sA
                         + (size_t)(rowBlock + baseRow) * sg.ldA + kc * 32 + kq * 4;
        const uint32_t* Wb = sg.W + (long long)z * sg.sW
                           + (size_t)(colBlock + baseRow) * sg.ldW + kc * 32 + kq * 4;
#pragma unroll
        for (int i = 0; i < 4; ++i) {
            sa[i] = *reinterpret_cast<const uint2*>(Ab + (size_t)i * 32 * sg.ldA);
            sw[i] = *reinterpret_cast<const uint4*>(Wb + (size_t)i * 32 * sg.ldW);
        }
    };

    auto sts_chunk = [&](int stage) {
        const uint32_t st = sb + stage * STAGE;
#pragma unroll
        for (int i = 0; i < 4; ++i) {
            // A: 4 halfs (8B)
            sts_v2(st + stsOff[i], sa[i].x, sa[i].y);
            // W: split packed into hi / lo fp16 pairs
            uint32_t h0 = __byte_perm(sw[i].x, sw[i].y, 0x7632);
            uint32_t l0 = __byte_perm(sw[i].x, sw[i].y, 0x5410);
            uint32_t h1 = __byte_perm(sw[i].z, sw[i].w, 0x7632);
            uint32_t l1 = __byte_perm(sw[i].z, sw[i].w, 0x5410);
            sts_v2(st + PIECE     + stsOff[i], h0, h1);
            sts_v2(st + 2 * PIECE + stsOff[i], l0, l1);
        }
    };

    auto compute = [&](int stage) {
        const uint32_t st = sb + stage * STAGE;
#pragma unroll
        for (int h = 0; h < 2; ++h) {
            const uint32_t hb = h * 32;
            uint32_t Aa[4][4], Bh[2][4], Bl[2][4];
#pragma unroll
            for (int mf = 0; mf < 4; ++mf)
                LDSM_X4(Aa[mf], st + aOff[mf] + hb);
#pragma unroll
            for (int p = 0; p < 2; ++p) {
                LDSM_X4(Bh[p], st + PIECE     + bOff[p] + hb);
                LDSM_X4(Bl[p], st + 2 * PIECE + bOff[p] + hb);
            }
#pragma unroll
            for (int mf = 0; mf < 4; ++mf)
#pragma unroll
                for (int nf = 0; nf < 4; ++nf) {
                    const int p = nf >> 1, s = nf & 1;
                    mma_f16(acc[mf][nf], Aa[mf], Bh[p][s], Bh[p][s + 2]);
                    mma_f16(acc[mf][nf], Aa[mf], Bl[p][s], Bl[p][s + 2]);
                }
        }
    };

    const int T = NSEG * 16;
    ldg_chunk(0);
    sts_chunk(0);
    __syncthreads();

#pragma unroll 1
    for (int t = 0; t < T; ++t) {
        const bool hasNext = (t + 1 < T);
        if (hasNext) ldg_chunk(t + 1);
        compute(t & 1);
        if (hasNext) {
            sts_chunk((t + 1) & 1);
            __syncthreads();
        }
    }

    // Epilogue
    const float* biasS = reinterpret_cast<const float*>(buf + OFF_BIAS);
    float* Cb = C + (long long)z * strideC;
#pragma unroll
    for (int mf = 0; mf < 4; ++mf) {
#pragma unroll
        for (int nf = 0; nf < 4; ++nf) {
            const int lcol = warp_n * 32 + nf * 8 + (lane & 3) * 2;
            const int r0   = rowBlock + warp_m * 64 + mf * 16 + (lane >> 2);
            const float b0 = biasS[lcol], b1 = biasS[lcol + 1];
            float2 v0 = {acc[mf][nf][0] + b0, acc[mf][nf][1] + b1};
            float2 v1 = {acc[mf][nf][2] + b0, acc[mf][nf][3] + b1};
            *reinterpret_cast<float2*>(Cb + (size_t)r0 * ldC + colBlock + lcol) = v0;
            *reinterpret_cast<float2*>(Cb + (size_t)(r0 + 8) * ldC + colBlock + lcol) = v1;
        }
    }
}

// ---------------------------------------------------------------------------
// LayerNorm + exact GELU: reads fp32 xs, writes fp16 xs_h
// ---------------------------------------------------------------------------
__global__ __launch_bounds__(128)
void ln_gelu_kernel(const float* __restrict__ xs,
                    __half* __restrict__ xs_h,
                    const float* __restrict__ ln_g,
                    const float* __restrict__ ln_b)
{
    using namespace cfg;
    __shared__ float shm[4];
    const long long row = blockIdx.x;
    const int s = (int)(row / B);
    const float* p = xs + row * D;
    const int t = threadIdx.x;

    float4 v = reinterpret_cast<const float4*>(p)[t];

    float sum = v.x + v.y + v.z + v.w;
#pragma unroll
    for (int o = 16; o; o >>= 1) sum += __shfl_xor_sync(0xffffffffu, sum, o);
    if ((t & 31) == 0) shm[t >> 5] = sum;
    __syncthreads();
    const float mean = (shm[0] + shm[1] + shm[2] + shm[3]) * (1.0f / D);
    __syncthreads();

    const float dx = v.x - mean, dy = v.y - mean, dz = v.z - mean, dw = v.w - mean;
    float ss = dx * dx + dy * dy + dz * dz + dw * dw;
#pragma unroll
    for (int o = 16; o; o >>= 1) ss += __shfl_xor_sync(0xffffffffu, ss, o);
    if ((t & 31) == 0) shm[t >> 5] = ss;
    __syncthreads();
    const float var = (shm[0] + shm[1] + shm[2] + shm[3]) * (1.0f / D);
    const float inv = rsqrtf(var + 1e-5f);

    const float4 g4 = reinterpret_cast<const float4*>(ln_g + (long long)s * D)[t];
    const float4 b4 = reinterpret_cast<const float4*>(ln_b + (long long)s * D)[t];

    const float kInvSqrt2 = 0.70710678118654752f;
    float y;
    float4 o4;
    y = dx * inv * g4.x + b4.x; o4.x = 0.5f * y * (1.0f + erff(y * kInvSqrt2));
    y = dy * inv * g4.y + b4.y; o4.y = 0.5f * y * (1.0f + erff(y * kInvSqrt2));
    y = dz * inv * g4.z + b4.z; o4.z = 0.5f * y * (1.0f + erff(y * kInvSqrt2));
    y = dw * inv * g4.w + b4.w; o4.w = 0.5f * y * (1.0f + erff(y * kInvSqrt2));
    reinterpret_cast<uint2*>(xs_h + row * D)[t] = pack_half4(o4);
}

// ---------------------------------------------------------------------------
// LSTM pointwise: gates -> h_new (fp32 out + fp16), c_new
// ---------------------------------------------------------------------------
__device__ __forceinline__ float sigmoidf_(float x) { return 1.0f / (1.0f + expf(-x)); }

__global__ __launch_bounds__(256)
void lstm_kernel(const float* __restrict__ gates,
                 const float* __restrict__ c_prev,
                 const float* __restrict__ decays,
                 float* __restrict__ h_new,
                 __half* __restrict__ hnew_h,
                 float* __restrict__ c_new)
{
    using namespace cfg;
    const long long idx = (long long)blockIdx.x * blockDim.x + threadIdx.x;
    const long long total = (long long)S * B * D;
    if (idx >= total) return;

    const int d = (int)(idx % D);
    const long long bs = idx / D;
    const int b = (int)(bs % B);
    const int s = (int)(bs / B);

    const float* g = gates + ((long long)s * B + b) * (4 * D) + d;
    const float ig = g[0];
    const float fg = g[D];
    const float gg = g[2 * D];
    const float og = g[3 * D];

    const float cp  = c_prev[idx];
    const float c_l = sigmoidf_(fg) * cp + sigmoidf_(ig) * tanhf(gg);
    const float h   = sigmoidf_(og) * tanhf(c_l);
    const float dd  = decays[s];

    h_new[idx]  = h;
    hnew_h[idx] = __float2half_rn(h);
    c_new[idx]  = dd * cp + (1.0f - dd) * c_l;
}

// ---------------------------------------------------------------------------
// Attention over S=3: one warp per (b, h) -> fp16 fused
// ---------------------------------------------------------------------------
__global__ __launch_bounds__(256)
void attn_kernel(const float* __restrict__ q,
                 const float* __restrict__ k,
                 const float* __restrict__ v,
                 __half* __restrict__ fused_h)
{
    using namespace cfg;
    const int gwarp = (int)((blockIdx.x * (long long)blockDim.x + threadIdx.x) >> 5);
    const int lane  = threadIdx.x & 31;
    if (gwarp >= B * H) return;
    const int h = gwarp % H;
    const int b = gwarp / H;

    const float* qp = q + (long long)b * D + h * HD;
    const float q0 = qp[lane];
    const float q1 = qp[lane + 32];

    float logits[S];
#pragma unroll
    for (int s = 0; s < S; s++) {
        const float* kp = k + ((long long)s * B + b) * D + h * HD;
        float dot = q0 * kp[lane] + q1 * kp[lane + 32];
#pragma unroll
        for (int o = 16; o; o >>= 1) dot += __shfl_xor_sync(0xffffffffu, dot, o);
        logits[s] = dot * 0.125f;
    }
    float mx = fmaxf(logits[0], fmaxf(logits[1], logits[2]));
    float e0 = expf(logits[0] - mx);
    float e1 = expf(logits[1] - mx);
    float e2 = expf(logits[2] - mx);
    const float rs = 1.0f / (e0 + e1 + e2);
    e0 *= rs; e1 *= rs; e2 *= rs;

    float o0 = 0.0f, o1 = 0.0f;
    const float w[S] = {e0, e1, e2};
#pragma unroll
    for (int s = 0; s < S; s++) {
        const float* vp = v + ((long long)s * B + b) * D + h * HD;
        o0 = fmaf(w[s], vp[lane],      o0);
        o1 = fmaf(w[s], vp[lane + 32], o1);
    }
    __half* fp = fused_h + (long long)b * D + h * HD;
    fp[lane]      = __float2half_rn(o0);
    fp[lane + 32] = __float2half_rn(o1);
}

// ---------------------------------------------------------------------------
// Launcher
// ---------------------------------------------------------------------------
extern "C" void kernel_launch(void* const* d_in, const int* in_sizes, int n_in,
                              void* d_out, int out_size)
{
    using namespace cfg;
    const float* x          = (const float*)d_in[0];
    const float* h_prev     = (const float*)d_in[1];
    const float* c_prev     = (const float*)d_in[2];
    const float* ssm_state  = (const float*)d_in[3];
    const float* Wt         = (const float*)d_in[4];
    const float* bt         = (const float*)d_in[5];
    const float* ln_g       = (const float*)d_in[6];
    const float* ln_b       = (const float*)d_in[7];
    const float* W_ih       = (const float*)d_in[8];
    const float* W_hh       = (const float*)d_in[9];
    const float* b_ih       = (const float*)d_in[10];
    const float* b_hh       = (const float*)d_in[11];
    const float* decays     = (const float*)d_in[12];
    const float* in_proj_w  = (const float*)d_in[13];
    const float* in_proj_b  = (const float*)d_in[14];
    const float* out_proj_w = (const float*)d_in[15];
    const float* out_proj_b = (const float*)d_in[16];
    const float* mix_w      = (const float*)d_in[17];
    const float* mix_b      = (const float*)d_in[18];

    float* out   = (float*)d_out;
    float* h_new = out + N_BD;
    float* c_new = h_new + N_SBD;

    float* scratch = nullptr;
    cudaGetSymbolAddress((void**)&scratch, g_scratch);
    float* xs    = scratch + XS_OFF;
    float* gates = scratch + GATES_OFF;
    float* qf    = scratch + QF_OFF;
    float* kf    = scratch + KF_OFF;
    float* vf    = scratch + VF_OFF;
    __half* x_h     = (__half*)(scratch + XH_OFF);
    __half* hprev_h = (__half*)(scratch + HPREVH_OFF);
    __half* xs_h    = (__half*)(scratch + XSH_OFF);
    __half* hnew_h  = (__half*)(scratch + HNEWH_OFF);
    __half* ssm_h   = (__half*)(scratch + SSMH_OFF);
    __half* fb_h    = (__half*)(scratch + FBH_OFF);
    uint32_t* Wt_p      = (uint32_t*)(scratch + WTP_OFF);
    uint32_t* Wih_p     = (uint32_t*)(scratch + WIHP_OFF);
    uint32_t* Whh_p     = (uint32_t*)(scratch + WHHP_OFF);
    uint32_t* inproj_p  = (uint32_t*)(scratch + INPROJP_OFF);
    uint32_t* outproj_p = (uint32_t*)(scratch + OUTPROJP_OFF);
    uint32_t* mix_p     = (uint32_t*)(scratch + MIXP_OFF);

    cudaFuncSetAttribute(mma_gemm_kernel<1>, cudaFuncAttributeMaxDynamicSharedMemorySize, SMEM_BYTES);
    cudaFuncSetAttribute(mma_gemm_kernel<2>, cudaFuncAttributeMaxDynamicSharedMemorySize, SMEM_BYTES);
    cudaFuncSetAttribute(mma_gemm_kernel<4>, cudaFuncAttributeMaxDynamicSharedMemorySize, SMEM_BYTES);

    const dim3 blk(256);

    // --- launch 0: pack all weights (hi|lo fp16) ---
    {
        CvtJobs<6> jobs;
        jobs.j[0] = {(const float4*)Wt,         Wt_p,      (long long)S * D * D / 4};
        jobs.j[1] = {(const float4*)W_ih,       Wih_p,     (long long)S * 4 * D * D / 4};
        jobs.j[2] = {(const float4*)W_hh,       Whh_p,     (long long)S * 4 * D * D / 4};
        jobs.j[3] = {(const float4*)in_proj_w,  inproj_p,  (long long)3 * D * D / 4};
        jobs.j[4] = {(const float4*)out_proj_w, outproj_p, (long long)D * D / 4};
        jobs.j[5] = {(const float4*)mix_w,      mix_p,     (long long)D * 3 * D / 4};
        long long tot = 0;
        for (int i = 0; i < 6; ++i) tot += jobs.j[i].n4;
        cvt_pack_kernel<6><<<(int)((tot + 255) / 256), 256>>>(jobs);
    }

    // --- launch 1: convert x -> fp16 ---
    {
        CvtJobs<1> jobs;
        jobs.j[0] = {(const float4*)x, x_h, N_BD / 4};
        cvt_half_kernel<1><<<(int)((N_BD / 4 + 255) / 256), 256>>>(jobs);
    }

    // --- launch 2: xs[s] = x @ Wt[s]^T + bt[s] ---
    {
        SegsH<1> sg;
        sg.s[0] = {x_h, Wt_p, bt, 0, (long long)D * D, D, D, D};
        mma_gemm_kernel<1><<<dim3(D / 128, B / 128, S), blk, SMEM_BYTES>>>(sg, xs, N_BD, D);
    }

    // --- launch 3: LN + GELU -> xs_h ---
    ln_gelu_kernel<<<S * B, 128>>>(xs, xs_h, ln_g, ln_b);

    // --- launch 4: convert h_prev + ssm_state -> fp16 ---
    {
        CvtJobs<2> jobs;
        jobs.j[0] = {(const float4*)h_prev,    hprev_h, N_SBD / 4};
        jobs.j[1] = {(const float4*)ssm_state, ssm_h,   N_BD / 4};
        long long tot = N_SBD / 4 + N_BD / 4;
        cvt_half_kernel<2><<<(int)((tot + 255) / 256), 256>>>(jobs);
    }

    // --- launch 5 (PROFILED): gates = xs@W_ih^T + b_ih + h_prev@W_hh^T + b_hh ---
    {
        SegsH<2> sg;
        sg.s[0] = {xs_h,    Wih_p, b_ih, N_SBD / S, (long long)4 * D * D, 4 * D, D, D};
        sg.s[1] = {hprev_h, Whh_p, b_hh, N_SBD / S, (long long)4 * D * D, 4 * D, D, D};
        mma_gemm_kernel<2><<<dim3(4 * D / 128, B / 128, S), blk, SMEM_BYTES>>>(
            sg, gates, (long long)B * 4 * D, 4 * D);
    }

    // --- launch 6: LSTM pointwise ---
    lstm_kernel<<<(int)((N_SBD + 255) / 256), 256>>>(
        gates, c_prev, decays, h_new, hnew_h, c_new);

    // --- launch 7/8: k, v ---
    {
        SegsH<1> sg;
        sg.s[0] = {hnew_h, inproj_p + (long long)D * D, in_proj_b + D, N_BD, 0, 0, D, D};
        mma_gemm_kernel<1><<<dim3(D / 128, B / 128, S), blk, SMEM_BYTES>>>(sg, kf, N_BD, D);
    }
    {
        SegsH<1> sg;
        sg.s[0] = {hnew_h, inproj_p + 2LL * D * D, in_proj_b + 2 * D, N_BD, 0, 0, D, D};
        mma_gemm_kernel<1><<<dim3(D / 128, B / 128, S), blk, SMEM_BYTES>>>(sg, vf, N_BD, D);
    }

    // --- launch 9: q ---
    {
        SegsH<1> sg;
        sg.s[0] = {ssm_h, inproj_p, in_proj_b, 0, 0, 0, D, D};
        mma_gemm_kernel<1><<<dim3(D / 128, B / 128, 1), blk, SMEM_BYTES>>>(sg, qf, 0, D);
    }

    // --- launch 10: attention -> fb_h ---
    attn_kernel<<<(B * H) / 8, 256>>>(qf, kf, vf, fb_h);

    // --- launch 11: out = fused@out_proj^T + sum_s h_new[s]@mix_w[:,sD:]^T + biases ---
    {
        SegsH<4> sg;
        sg.s[0] = {fb_h,               outproj_p,     out_proj_b, 0, 0, 0, D, D};
        sg.s[1] = {hnew_h,             mix_p,         mix_b,      0, 0, 0, D, S * D};
        sg.s[2] = {hnew_h + N_BD,      mix_p + D,     nullptr,    0, 0, 0, D, S * D};
        sg.s[3] = {hnew_h + 2 * N_BD,  mix_p + 2 * D, nullptr,    0, 0, 0, D, S * D};
        mma_gemm_kernel<4><<<dim3(D / 128, B / 128, 1), blk, SMEM_BYTES>>>(sg, out, 0, D);
    }
}

// round 5
// speedup vs baseline: 5.4912x; 1.6260x over previous
#include <cuda_runtime.h>
#include <cuda_fp16.h>
#include <cstdint>
#include <math.h>

// ---------------------------------------------------------------------------
// EnhancedXLSTM — round 5: mma.sync fp16 single-term (A fp16, W fp16),
// double-buffered smem, 2 CTAs/SM.
//   B=16384, D=512, S=3, H=8, HD=64
// ---------------------------------------------------------------------------

namespace cfg {
constexpr int B  = 16384;
constexpr int D  = 512;
constexpr int S  = 3;
constexpr int H  = 8;
constexpr int HD = 64;

constexpr long long N_BD  = (long long)B * D;
constexpr long long N_SBD = (long long)S * B * D;

// fp32 scratch (float units)
constexpr long long XS_OFF     = 0;
constexpr long long GATES_OFF  = XS_OFF    + N_SBD;
constexpr long long QF_OFF     = GATES_OFF + 4 * N_SBD;
constexpr long long KF_OFF     = QF_OFF    + N_BD;
constexpr long long VF_OFF     = KF_OFF    + N_SBD;
// fp16 activation scratch (float units)
constexpr long long XH_OFF     = VF_OFF    + N_SBD;
constexpr long long HPREVH_OFF = XH_OFF    + N_BD / 2;
constexpr long long XSH_OFF    = HPREVH_OFF + N_SBD / 2;
constexpr long long HNEWH_OFF  = XSH_OFF   + N_SBD / 2;
constexpr long long SSMH_OFF   = HNEWH_OFF + N_SBD / 2;
constexpr long long FBH_OFF    = SSMH_OFF  + N_BD / 2;
// fp16 weight scratch (float units)
constexpr long long WTH_OFF     = FBH_OFF   + N_BD / 2;
constexpr long long WIHH_OFF    = WTH_OFF   + (long long)S * D * D / 2;
constexpr long long WHHH_OFF    = WIHH_OFF  + (long long)S * 4 * D * D / 2;
constexpr long long INPROJH_OFF = WHHH_OFF  + (long long)S * 4 * D * D / 2;
constexpr long long OUTPROJH_OFF= INPROJH_OFF + (long long)3 * D * D / 2;
constexpr long long MIXH_OFF    = OUTPROJH_OFF + (long long)D * D / 2;
constexpr long long SCRATCH_TOTAL = MIXH_OFF + (long long)D * 3 * D / 2;
}

__device__ float g_scratch[cfg::SCRATCH_TOTAL];

// ---------------------------------------------------------------------------
// Conversion helpers
// ---------------------------------------------------------------------------
__device__ __forceinline__ uint2 pack_half4(float4 v) {
    __half2 p0 = __floats2half2_rn(v.x, v.y);
    __half2 p1 = __floats2half2_rn(v.z, v.w);
    uint2 o;
    o.x = *reinterpret_cast<uint32_t*>(&p0);
    o.y = *reinterpret_cast<uint32_t*>(&p1);
    return o;
}

struct CvtJob { const float4* src; void* dst; long long n4; };
template <int NJ> struct CvtJobs { CvtJob j[NJ]; };

template <int NJ>
__global__ __launch_bounds__(256)
void cvt_half_kernel(CvtJobs<NJ> jobs)
{
    long long i = (long long)blockIdx.x * blockDim.x + threadIdx.x;
#pragma unroll
    for (int jj = 0; jj < NJ; ++jj) {
        const CvtJob J = jobs.j[jj];
        if (i < J.n4) {
            ((uint2*)J.dst)[i] = pack_half4(J.src[i]);
            return;
        }
        i -= J.n4;
    }
}

// ---------------------------------------------------------------------------
// MMA helpers
// ---------------------------------------------------------------------------
__device__ __forceinline__ uint32_t smem_u32(const void* p) {
    uint32_t a;
    asm("{ .reg .u64 t; cvta.to.shared.u64 t, %1; cvt.u32.u64 %0, t; }" : "=r"(a) : "l"(p));
    return a;
}

#define LDSM_X4(r, addr) \
    asm volatile("ldmatrix.sync.aligned.m8n8.x4.shared.b16 {%0,%1,%2,%3}, [%4];" \
                 : "=r"((r)[0]), "=r"((r)[1]), "=r"((r)[2]), "=r"((r)[3]) : "r"(addr))

__device__ __forceinline__ void mma_f16(float* c, const uint32_t* a, uint32_t b0, uint32_t b1) {
    asm volatile(
        "mma.sync.aligned.m16n8k16.row.col.f32.f16.f16.f32 "
        "{%0,%1,%2,%3}, {%4,%5,%6,%7}, {%8,%9}, {%0,%1,%2,%3};"
        : "+f"(c[0]), "+f"(c[1]), "+f"(c[2]), "+f"(c[3])
        : "r"(a[0]), "r"(a[1]), "r"(a[2]), "r"(a[3]), "r"(b0), "r"(b1));
}

__device__ __forceinline__ void sts_v2(uint32_t addr, uint32_t w0, uint32_t w1) {
    asm volatile("st.shared.v2.b32 [%0], {%1,%2};" :: "r"(addr), "r"(w0), "r"(w1) : "memory");
}

// ---------------------------------------------------------------------------
// GEMM:  C[z][M,N] = sum_seg A_seg[z][M,512] @ W_seg[z][N,512]^T + sum bias
//   A, W: fp16.  Tile 128x128, 256 thr, warp tile 64x32, K-chunk 32,
//   double-buffered smem. 1 MMA per position.
// ---------------------------------------------------------------------------
struct SegH {
    const __half* A; const __half* W; const float* bias;
    long long sA, sW, sB;
    int ldA, ldW;
};
template <int NSEG> struct SegsH { SegH s[NSEG]; };

constexpr int ROW_STRIDE = 80;               // bytes per row (32 halfs + pad)
constexpr int PIECE = 128 * ROW_STRIDE;      // 10240
constexpr int STAGE = 2 * PIECE;             // A + B  = 20480
constexpr int OFF_BIAS = 2 * STAGE;          // 40960
constexpr int SMEM_BYTES = OFF_BIAS + 512;   // 41472

template <int NSEG>
__global__ __launch_bounds__(256, 2)
void mma_gemm_kernel(SegsH<NSEG> segs, float* __restrict__ C,
                     long long strideC, int ldC)
{
    extern __shared__ __align__(16) uint8_t buf[];
    const uint32_t sb = smem_u32(buf);

    const int tid  = threadIdx.x;
    const int wid  = tid >> 5;
    const int lane = tid & 31;
    const int z = blockIdx.z;
    const int rowBlock = blockIdx.y * 128;
    const int colBlock = blockIdx.x * 128;

    // Bias sum for this column block
    if (tid < 128) {
        float acc = 0.0f;
#pragma unroll
        for (int sgi = 0; sgi < NSEG; ++sgi) {
            const SegH& sg = segs.s[sgi];
            if (sg.bias) acc += sg.bias[z * sg.sB + colBlock + tid];
        }
        reinterpret_cast<float*>(buf + OFF_BIAS)[tid] = acc;
    }

    // Loader mapping: thread -> (baseRow, kq); rows baseRow + 32*i, quad kq
    const int baseRow = tid >> 3;     // 0..31
    const int kq      = tid & 7;      // 4-half quad within 32-wide K chunk
    uint32_t stsOff[4];
#pragma unroll
    for (int i = 0; i < 4; ++i)
        stsOff[i] = (uint32_t)((baseRow + i * 32) * ROW_STRIDE + kq * 8);

    // ldmatrix mapping
    const int warp_m = wid >> 2;
    const int warp_n = wid & 3;
    const int xrow    = (lane & 7) | (((lane >> 3) & 1) << 3);
    const int kb_lane = ((lane >> 4) & 1) * 16;
    uint32_t aOff[4], bOff[2];
#pragma unroll
    for (int mf = 0; mf < 4; ++mf)
        aOff[mf] = (uint32_t)((warp_m * 64 + mf * 16 + xrow) * ROW_STRIDE + kb_lane);
#pragma unroll
    for (int p = 0; p < 2; ++p)
        bOff[p] = (uint32_t)((warp_n * 32 + p * 16 + xrow) * ROW_STRIDE + kb_lane);

    float acc[4][4][4];
#pragma unroll
    for (int mf = 0; mf < 4; ++mf)
#pragma unroll
        for (int nf = 0; nf < 4; ++nf)
#pragma unroll
            for (int e = 0; e < 4; ++e) acc[mf][nf][e] = 0.0f;

    uint2 sa[4], sw[4];

    auto ldg_chunk = [&](int t) {
        const int sgi = t >> 4;
        const int kc  = t & 15;
        const SegH& sg = segs.s[sgi];
        const __half* Ab = sg.A + (long long)z * sg.sA
                         + (size_t)(rowBlock + baseRow) * sg.ldA + kc * 32 + kq * 4;
        const __half* Wb = sg.W + (long long)z * sg.sW
                         + (size_t)(colBlock + baseRow) * sg.ldW + kc * 32 + kq * 4;
#pragma unroll
        for (int i = 0; i < 4; ++i) {
            sa[i] = *reinterpret_cast<const uint2*>(Ab + (size_t)i * 32 * sg.ldA);
            sw[i] = *reinterpret_cast<const uint2*>(Wb + (size_t)i * 32 * sg.ldW);
        }
    };

    auto sts_chunk = [&](int stage) {
        const uint32_t st = sb + stage * STAGE;
#pragma unroll
        for (int i = 0; i < 4; ++i) {
            sts_v2(st         + stsOff[i], sa[i].x, sa[i].y);
            sts_v2(st + PIECE + stsOff[i], sw[i].x, sw[i].y);
        }
    };

    auto compute = [&](int stage) {
        const uint32_t st = sb + stage * STAGE;
#pragma unroll
        for (int h = 0; h < 2; ++h) {
            const uint32_t hb = h * 32;
            uint32_t Aa[4][4], Bb[2][4];
#pragma unroll
            for (int mf = 0; mf < 4; ++mf)
                LDSM_X4(Aa[mf], st + aOff[mf] + hb);
#pragma unroll
            for (int p = 0; p < 2; ++p)
                LDSM_X4(Bb[p], st + PIECE + bOff[p] + hb);
#pragma unroll
            for (int mf = 0; mf < 4; ++mf)
#pragma unroll
                for (int nf = 0; nf < 4; ++nf) {
                    const int p = nf >> 1, s = nf & 1;
                    mma_f16(acc[mf][nf], Aa[mf], Bb[p][s], Bb[p][s + 2]);
                }
        }
    };

    const int T = NSEG * 16;
    ldg_chunk(0);
    sts_chunk(0);
    __syncthreads();

#pragma unroll 1
    for (int t = 0; t < T; ++t) {
        const bool hasNext = (t + 1 < T);
        if (hasNext) ldg_chunk(t + 1);
        compute(t & 1);
        if (hasNext) {
            sts_chunk((t + 1) & 1);
            __syncthreads();
        }
    }

    // Epilogue
    const float* biasS = reinterpret_cast<const float*>(buf + OFF_BIAS);
    float* Cb = C + (long long)z * strideC;
#pragma unroll
    for (int mf = 0; mf < 4; ++mf) {
#pragma unroll
        for (int nf = 0; nf < 4; ++nf) {
            const int lcol = warp_n * 32 + nf * 8 + (lane & 3) * 2;
            const int r0   = rowBlock + warp_m * 64 + mf * 16 + (lane >> 2);
            const float b0 = biasS[lcol], b1 = biasS[lcol + 1];
            float2 v0 = {acc[mf][nf][0] + b0, acc[mf][nf][1] + b1};
            float2 v1 = {acc[mf][nf][2] + b0, acc[mf][nf][3] + b1};
            *reinterpret_cast<float2*>(Cb + (size_t)r0 * ldC + colBlock + lcol) = v0;
            *reinterpret_cast<float2*>(Cb + (size_t)(r0 + 8) * ldC + colBlock + lcol) = v1;
        }
    }
}

// ---------------------------------------------------------------------------
// LayerNorm + exact GELU: reads fp32 xs, writes fp16 xs_h
// ---------------------------------------------------------------------------
__global__ __launch_bounds__(128)
void ln_gelu_kernel(const float* __restrict__ xs,
                    __half* __restrict__ xs_h,
                    const float* __restrict__ ln_g,
                    const float* __restrict__ ln_b)
{
    using namespace cfg;
    __shared__ float shm[4];
    const long long row = blockIdx.x;
    const int s = (int)(row / B);
    const float* p = xs + row * D;
    const int t = threadIdx.x;

    float4 v = reinterpret_cast<const float4*>(p)[t];

    float sum = v.x + v.y + v.z + v.w;
#pragma unroll
    for (int o = 16; o; o >>= 1) sum += __shfl_xor_sync(0xffffffffu, sum, o);
    if ((t & 31) == 0) shm[t >> 5] = sum;
    __syncthreads();
    const float mean = (shm[0] + shm[1] + shm[2] + shm[3]) * (1.0f / D);
    __syncthreads();

    const float dx = v.x - mean, dy = v.y - mean, dz = v.z - mean, dw = v.w - mean;
    float ss = dx * dx + dy * dy + dz * dz + dw * dw;
#pragma unroll
    for (int o = 16; o; o >>= 1) ss += __shfl_xor_sync(0xffffffffu, ss, o);
    if ((t & 31) == 0) shm[t >> 5] = ss;
    __syncthreads();
    const float var = (shm[0] + shm[1] + shm[2] + shm[3]) * (1.0f / D);
    const float inv = rsqrtf(var + 1e-5f);

    const float4 g4 = reinterpret_cast<const float4*>(ln_g + (long long)s * D)[t];
    const float4 b4 = reinterpret_cast<const float4*>(ln_b + (long long)s * D)[t];

    const float kInvSqrt2 = 0.70710678118654752f;
    float y;
    float4 o4;
    y = dx * inv * g4.x + b4.x; o4.x = 0.5f * y * (1.0f + erff(y * kInvSqrt2));
    y = dy * inv * g4.y + b4.y; o4.y = 0.5f * y * (1.0f + erff(y * kInvSqrt2));
    y = dz * inv * g4.z + b4.z; o4.z = 0.5f * y * (1.0f + erff(y * kInvSqrt2));
    y = dw * inv * g4.w + b4.w; o4.w = 0.5f * y * (1.0f + erff(y * kInvSqrt2));
    reinterpret_cast<uint2*>(xs_h + row * D)[t] = pack_half4(o4);
}

// ---------------------------------------------------------------------------
// LSTM pointwise: gates -> h_new (fp32 + fp16), c_new
// ---------------------------------------------------------------------------
__device__ __forceinline__ float sigmoidf_(float x) { return 1.0f / (1.0f + expf(-x)); }

__global__ __launch_bounds__(256)
void lstm_kernel(const float* __restrict__ gates,
                 const float* __restrict__ c_prev,
                 const float* __restrict__ decays,
                 float* __restrict__ h_new,
                 __half* __restrict__ hnew_h,
                 float* __restrict__ c_new)
{
    using namespace cfg;
    const long long idx = (long long)blockIdx.x * blockDim.x + threadIdx.x;
    const long long total = (long long)S * B * D;
    if (idx >= total) return;

    const int d = (int)(idx % D);
    const long long bs = idx / D;
    const int b = (int)(bs % B);
    const int s = (int)(bs / B);

    const float* g = gates + ((long long)s * B + b) * (4 * D) + d;
    const float ig = g[0];
    const float fg = g[D];
    const float gg = g[2 * D];
    const float og = g[3 * D];

    const float cp  = c_prev[idx];
    const float c_l = sigmoidf_(fg) * cp + sigmoidf_(ig) * tanhf(gg);
    const float h   = sigmoidf_(og) * tanhf(c_l);
    const float dd  = decays[s];

    h_new[idx]  = h;
    hnew_h[idx] = __float2half_rn(h);
    c_new[idx]  = dd * cp + (1.0f - dd) * c_l;
}

// ---------------------------------------------------------------------------
// Attention over S=3: one warp per (b, h) -> fp16 fused
// ---------------------------------------------------------------------------
__global__ __launch_bounds__(256)
void attn_kernel(const float* __restrict__ q,
                 const float* __restrict__ k,
                 const float* __restrict__ v,
                 __half* __restrict__ fused_h)
{
    using namespace cfg;
    const int gwarp = (int)((blockIdx.x * (long long)blockDim.x + threadIdx.x) >> 5);
    const int lane  = threadIdx.x & 31;
    if (gwarp >= B * H) return;
    const int h = gwarp % H;
    const int b = gwarp / H;

    const float* qp = q + (long long)b * D + h * HD;
    const float q0 = qp[lane];
    const float q1 = qp[lane + 32];

    float logits[S];
#pragma unroll
    for (int s = 0; s < S; s++) {
        const float* kp = k + ((long long)s * B + b) * D + h * HD;
        float dot = q0 * kp[lane] + q1 * kp[lane + 32];
#pragma unroll
        for (int o = 16; o; o >>= 1) dot += __shfl_xor_sync(0xffffffffu, dot, o);
        logits[s] = dot * 0.125f;
    }
    float mx = fmaxf(logits[0], fmaxf(logits[1], logits[2]));
    float e0 = expf(logits[0] - mx);
    float e1 = expf(logits[1] - mx);
    float e2 = expf(logits[2] - mx);
    const float rs = 1.0f / (e0 + e1 + e2);
    e0 *= rs; e1 *= rs; e2 *= rs;

    float o0 = 0.0f, o1 = 0.0f;
    const float w[S] = {e0, e1, e2};
#pragma unroll
    for (int s = 0; s < S; s++) {
        const float* vp = v + ((long long)s * B + b) * D + h * HD;
        o0 = fmaf(w[s], vp[lane],      o0);
        o1 = fmaf(w[s], vp[lane + 32], o1);
    }
    __half* fp = fused_h + (long long)b * D + h * HD;
    fp[lane]      = __float2half_rn(o0);
    fp[lane + 32] = __float2half_rn(o1);
}

// ---------------------------------------------------------------------------
// Launcher
// ---------------------------------------------------------------------------
extern "C" void kernel_launch(void* const* d_in, const int* in_sizes, int n_in,
                              void* d_out, int out_size)
{
    using namespace cfg;
    const float* x          = (const float*)d_in[0];
    const float* h_prev     = (const float*)d_in[1];
    const float* c_prev     = (const float*)d_in[2];
    const float* ssm_state  = (const float*)d_in[3];
    const float* Wt         = (const float*)d_in[4];
    const float* bt         = (const float*)d_in[5];
    const float* ln_g       = (const float*)d_in[6];
    const float* ln_b       = (const float*)d_in[7];
    const float* W_ih       = (const float*)d_in[8];
    const float* W_hh       = (const float*)d_in[9];
    const float* b_ih       = (const float*)d_in[10];
    const float* b_hh       = (const float*)d_in[11];
    const float* decays     = (const float*)d_in[12];
    const float* in_proj_w  = (const float*)d_in[13];
    const float* in_proj_b  = (const float*)d_in[14];
    const float* out_proj_w = (const float*)d_in[15];
    const float* out_proj_b = (const float*)d_in[16];
    const float* mix_w      = (const float*)d_in[17];
    const float* mix_b      = (const float*)d_in[18];

    float* out   = (float*)d_out;
    float* h_new = out + N_BD;
    float* c_new = h_new + N_SBD;

    float* scratch = nullptr;
    cudaGetSymbolAddress((void**)&scratch, g_scratch);
    float* xs    = scratch + XS_OFF;
    float* gates = scratch + GATES_OFF;
    float* qf    = scratch + QF_OFF;
    float* kf    = scratch + KF_OFF;
    float* vf    = scratch + VF_OFF;
    __half* x_h     = (__half*)(scratch + XH_OFF);
    __half* hprev_h = (__half*)(scratch + HPREVH_OFF);
    __half* xs_h    = (__half*)(scratch + XSH_OFF);
    __half* hnew_h  = (__half*)(scratch + HNEWH_OFF);
    __half* ssm_h   = (__half*)(scratch + SSMH_OFF);
    __half* fb_h    = (__half*)(scratch + FBH_OFF);
    __half* Wt_h      = (__half*)(scratch + WTH_OFF);
    __half* Wih_h     = (__half*)(scratch + WIHH_OFF);
    __half* Whh_h     = (__half*)(scratch + WHHH_OFF);
    __half* inproj_h  = (__half*)(scratch + INPROJH_OFF);
    __half* outproj_h = (__half*)(scratch + OUTPROJH_OFF);
    __half* mix_h     = (__half*)(scratch + MIXH_OFF);

    cudaFuncSetAttribute(mma_gemm_kernel<1>, cudaFuncAttributeMaxDynamicSharedMemorySize, SMEM_BYTES);
    cudaFuncSetAttribute(mma_gemm_kernel<2>, cudaFuncAttributeMaxDynamicSharedMemorySize, SMEM_BYTES);
    cudaFuncSetAttribute(mma_gemm_kernel<4>, cudaFuncAttributeMaxDynamicSharedMemorySize, SMEM_BYTES);

    const dim3 blk(256);

    // --- launch 0: convert weights + x + h_prev + ssm to fp16 ---
    {
        CvtJobs<9> jobs;
        jobs.j[0] = {(const float4*)Wt,         Wt_h,      (long long)S * D * D / 4};
        jobs.j[1] = {(const float4*)W_ih,       Wih_h,     (long long)S * 4 * D * D / 4};
        jobs.j[2] = {(const float4*)W_hh,       Whh_h,     (long long)S * 4 * D * D / 4};
        jobs.j[3] = {(const float4*)in_proj_w,  inproj_h,  (long long)3 * D * D / 4};
        jobs.j[4] = {(const float4*)out_proj_w, outproj_h, (long long)D * D / 4};
        jobs.j[5] = {(const float4*)mix_w,      mix_h,     (long long)D * 3 * D / 4};
        jobs.j[6] = {(const float4*)x,          x_h,       N_BD / 4};
        jobs.j[7] = {(const float4*)h_prev,     hprev_h,   N_SBD / 4};
        jobs.j[8] = {(const float4*)ssm_state,  ssm_h,     N_BD / 4};
        long long tot = 0;
        for (int i = 0; i < 9; ++i) tot += jobs.j[i].n4;
        cvt_half_kernel<9><<<(int)((tot + 255) / 256), 256>>>(jobs);
    }

    // --- launch 1: xs[s] = x @ Wt[s]^T + bt[s] ---
    {
        SegsH<1> sg;
        sg.s[0] = {x_h, Wt_h, bt, 0, (long long)D * D, D, D, D};
        mma_gemm_kernel<1><<<dim3(D / 128, B / 128, S), blk, SMEM_BYTES>>>(sg, xs, N_BD, D);
    }

    // --- launch 2: LN + GELU -> xs_h ---
    ln_gelu_kernel<<<S * B, 128>>>(xs, xs_h, ln_g, ln_b);

    // --- launch 3: gates = xs@W_ih^T + b_ih + h_prev@W_hh^T + b_hh ---
    {
        SegsH<2> sg;
        sg.s[0] = {xs_h,    Wih_h, b_ih, N_BD, (long long)4 * D * D, 4 * D, D, D};
        sg.s[1] = {hprev_h, Whh_h, b_hh, N_BD, (long long)4 * D * D, 4 * D, D, D};
        mma_gemm_kernel<2><<<dim3(4 * D / 128, B / 128, S), blk, SMEM_BYTES>>>(
            sg, gates, (long long)B * 4 * D, 4 * D);
    }

    // --- launch 4: LSTM pointwise ---
    lstm_kernel<<<(int)((N_SBD + 255) / 256), 256>>>(
        gates, c_prev, decays, h_new, hnew_h, c_new);

    // --- launch 5: k (profiled target) ---
    {
        SegsH<1> sg;
        sg.s[0] = {hnew_h, inproj_h + (long long)D * D, in_proj_b + D, N_BD, 0, 0, D, D};
        mma_gemm_kernel<1><<<dim3(D / 128, B / 128, S), blk, SMEM_BYTES>>>(sg, kf, N_BD, D);
    }
    // --- launch 6: v ---
    {
        SegsH<1> sg;
        sg.s[0] = {hnew_h, inproj_h + 2LL * D * D, in_proj_b + 2 * D, N_BD, 0, 0, D, D};
        mma_gemm_kernel<1><<<dim3(D / 128, B / 128, S), blk, SMEM_BYTES>>>(sg, vf, N_BD, D);
    }
    // --- launch 7: q ---
    {
        SegsH<1> sg;
        sg.s[0] = {ssm_h, inproj_h, in_proj_b, 0, 0, 0, D, D};
        mma_gemm_kernel<1><<<dim3(D / 128, B / 128, 1), blk, SMEM_BYTES>>>(sg, qf, 0, D);
    }

    // --- launch 8: attention -> fb_h ---
    attn_kernel<<<(B * H) / 8, 256>>>(qf, kf, vf, fb_h);

    // --- launch 9: out = fused@out_proj^T + sum_s h_new[s]@mix_w[:,sD:]^T + biases ---
    {
        SegsH<4> sg;
        sg.s[0] = {fb_h,               outproj_h,     out_proj_b, 0, 0, 0, D, D};
        sg.s[1] = {hnew_h,             mix_h,         mix_b,      0, 0, 0, D, S * D};
        sg.s[2] = {hnew_h + N_BD,      mix_h + D,     nullptr,    0, 0, 0, D, S * D};
        sg.s[3] = {hnew_h + 2 * N_BD,  mix_h + 2 * D, nullptr,    0, 0, 0, D, S * D};
        mma_gemm_kernel<4><<<dim3(D / 128, B / 128, 1), blk, SMEM_BYTES>>>(sg, out, 0, D);
    }
}

// round 6
// speedup vs baseline: 5.5019x; 1.0019x over previous
#include <cuda_runtime.h>
#include <cuda_fp16.h>
#include <cstdint>
#include <math.h>

// ---------------------------------------------------------------------------
// EnhancedXLSTM — round 5: mma.sync fp16 single-term (A fp16, W fp16),
// double-buffered smem, 2 CTAs/SM.
//   B=16384, D=512, S=3, H=8, HD=64
// ---------------------------------------------------------------------------

namespace cfg {
constexpr int B  = 16384;
constexpr int D  = 512;
constexpr int S  = 3;
constexpr int H  = 8;
constexpr int HD = 64;

constexpr long long N_BD  = (long long)B * D;
constexpr long long N_SBD = (long long)S * B * D;

// fp32 scratch (float units)
constexpr long long XS_OFF     = 0;
constexpr long long GATES_OFF  = XS_OFF    + N_SBD;
constexpr long long QF_OFF     = GATES_OFF + 4 * N_SBD;
constexpr long long KF_OFF     = QF_OFF    + N_BD;
constexpr long long VF_OFF     = KF_OFF    + N_SBD;
// fp16 activation scratch (float units)
constexpr long long XH_OFF     = VF_OFF    + N_SBD;
constexpr long long HPREVH_OFF = XH_OFF    + N_BD / 2;
constexpr long long XSH_OFF    = HPREVH_OFF + N_SBD / 2;
constexpr long long HNEWH_OFF  = XSH_OFF   + N_SBD / 2;
constexpr long long SSMH_OFF   = HNEWH_OFF + N_SBD / 2;
constexpr long long FBH_OFF    = SSMH_OFF  + N_BD / 2;
// fp16 weight scratch (float units)
constexpr long long WTH_OFF     = FBH_OFF   + N_BD / 2;
constexpr long long WIHH_OFF    = WTH_OFF   + (long long)S * D * D / 2;
constexpr long long WHHH_OFF    = WIHH_OFF  + (long long)S * 4 * D * D / 2;
constexpr long long INPROJH_OFF = WHHH_OFF  + (long long)S * 4 * D * D / 2;
constexpr long long OUTPROJH_OFF= INPROJH_OFF + (long long)3 * D * D / 2;
constexpr long long MIXH_OFF    = OUTPROJH_OFF + (long long)D * D / 2;
constexpr long long SCRATCH_TOTAL = MIXH_OFF + (long long)D * 3 * D / 2;
}

__device__ float g_scratch[cfg::SCRATCH_TOTAL];

// ---------------------------------------------------------------------------
// Conversion helpers
// ---------------------------------------------------------------------------
__device__ __forceinline__ uint2 pack_half4(float4 v) {
    __half2 p0 = __floats2half2_rn(v.x, v.y);
    __half2 p1 = __floats2half2_rn(v.z, v.w);
    uint2 o;
    o.x = *reinterpret_cast<uint32_t*>(&p0);
    o.y = *reinterpret_cast<uint32_t*>(&p1);
    return o;
}

struct CvtJob { const float4* src; void* dst; long long n4; };
template <int NJ> struct CvtJobs { CvtJob j[NJ]; };

template <int NJ>
__global__ __launch_bounds__(256)
void cvt_half_kernel(CvtJobs<NJ> jobs)
{
    long long i = (long long)blockIdx.x * blockDim.x + threadIdx.x;
#pragma unroll
    for (int jj = 0; jj < NJ; ++jj) {
        const CvtJob J = jobs.j[jj];
        if (i < J.n4) {
            ((uint2*)J.dst)[i] = pack_half4(J.src[i]);
            return;
        }
        i -= J.n4;
    }
}

// ---------------------------------------------------------------------------
// MMA helpers
// ---------------------------------------------------------------------------
__device__ __forceinline__ uint32_t smem_u32(const void* p) {
    uint32_t a;
    asm("{ .reg .u64 t; cvta.to.shared.u64 t, %1; cvt.u32.u64 %0, t; }" : "=r"(a) : "l"(p));
    return a;
}

#define LDSM_X4(r, addr) \
    asm volatile("ldmatrix.sync.aligned.m8n8.x4.shared.b16 {%0,%1,%2,%3}, [%4];" \
                 : "=r"((r)[0]), "=r"((r)[1]), "=r"((r)[2]), "=r"((r)[3]) : "r"(addr))

__device__ __forceinline__ void mma_f16(float* c, const uint32_t* a, uint32_t b0, uint32_t b1) {
    asm volatile(
        "mma.sync.aligned.m16n8k16.row.col.f32.f16.f16.f32 "
        "{%0,%1,%2,%3}, {%4,%5,%6,%7}, {%8,%9}, {%0,%1,%2,%3};"
        : "+f"(c[0]), "+f"(c[1]), "+f"(c[2]), "+f"(c[3])
        : "r"(a[0]), "r"(a[1]), "r"(a[2]), "r"(a[3]), "r"(b0), "r"(b1));
}

__device__ __forceinline__ void sts_v2(uint32_t addr, uint32_t w0, uint32_t w1) {
    asm volatile("st.shared.v2.b32 [%0], {%1,%2};" :: "r"(addr), "r"(w0), "r"(w1) : "memory");
}

// ---------------------------------------------------------------------------
// GEMM:  C[z][M,N] = sum_seg A_seg[z][M,512] @ W_seg[z][N,512]^T + sum bias
//   A, W: fp16.  Tile 128x128, 256 thr, warp tile 64x32, K-chunk 32,
//   double-buffered smem. 1 MMA per position.
// ---------------------------------------------------------------------------
struct SegH {
    const __half* A; const __half* W; const float* bias;
    long long sA, sW, sB;
    int ldA, ldW;
};
template <int NSEG> struct SegsH { SegH s[NSEG]; };

constexpr int ROW_STRIDE = 80;               // bytes per row (32 halfs + pad)
constexpr int PIECE = 128 * ROW_STRIDE;      // 10240
constexpr int STAGE = 2 * PIECE;             // A + B  = 20480
constexpr int OFF_BIAS = 2 * STAGE;          // 40960
constexpr int SMEM_BYTES = OFF_BIAS + 512;   // 41472

template <int NSEG>
__global__ __launch_bounds__(256, 2)
void mma_gemm_kernel(SegsH<NSEG> segs, float* __restrict__ C,
                     long long strideC, int ldC)
{
    extern __shared__ __align__(16) uint8_t buf[];
    const uint32_t sb = smem_u32(buf);

    const int tid  = threadIdx.x;
    const int wid  = tid >> 5;
    const int lane = tid & 31;
    const int z = blockIdx.z;
    const int rowBlock = blockIdx.y * 128;
    const int colBlock = blockIdx.x * 128;

    // Bias sum for this column block
    if (tid < 128) {
        float acc = 0.0f;
#pragma unroll
        for (int sgi = 0; sgi < NSEG; ++sgi) {
            const SegH& sg = segs.s[sgi];
            if (sg.bias) acc += sg.bias[z * sg.sB + colBlock + tid];
        }
        reinterpret_cast<float*>(buf + OFF_BIAS)[tid] = acc;
    }

    // Loader mapping: thread -> (baseRow, kq); rows baseRow + 32*i, quad kq
    const int baseRow = tid >> 3;     // 0..31
    const int kq      = tid & 7;      // 4-half quad within 32-wide K chunk
    uint32_t stsOff[4];
#pragma unroll
    for (int i = 0; i < 4; ++i)
        stsOff[i] = (uint32_t)((baseRow + i * 32) * ROW_STRIDE + kq * 8);

    // ldmatrix mapping
    const int warp_m = wid >> 2;
    const int warp_n = wid & 3;
    const int xrow    = (lane & 7) | (((lane >> 3) & 1) << 3);
    const int kb_lane = ((lane >> 4) & 1) * 16;
    uint32_t aOff[4], bOff[2];
#pragma unroll
    for (int mf = 0; mf < 4; ++mf)
        aOff[mf] = (uint32_t)((warp_m * 64 + mf * 16 + xrow) * ROW_STRIDE + kb_lane);
#pragma unroll
    for (int p = 0; p < 2; ++p)
        bOff[p] = (uint32_t)((warp_n * 32 + p * 16 + xrow) * ROW_STRIDE + kb_lane);

    float acc[4][4][4];
#pragma unroll
    for (int mf = 0; mf < 4; ++mf)
#pragma unroll
        for (int nf = 0; nf < 4; ++nf)
#pragma unroll
            for (int e = 0; e < 4; ++e) acc[mf][nf][e] = 0.0f;

    uint2 sa[4], sw[4];

    auto ldg_chunk = [&](int t) {
        const int sgi = t >> 4;
        const int kc  = t & 15;
        const SegH& sg = segs.s[sgi];
        const __half* Ab = sg.A + (long long)z * sg.sA
                         + (size_t)(rowBlock + baseRow) * sg.ldA + kc * 32 + kq * 4;
        const __half* Wb = sg.W + (long long)z * sg.sW
                         + (size_t)(colBlock + baseRow) * sg.ldW + kc * 32 + kq * 4;
#pragma unroll
        for (int i = 0; i < 4; ++i) {
            sa[i] = *reinterpret_cast<const uint2*>(Ab + (size_t)i * 32 * sg.ldA);
            sw[i] = *reinterpret_cast<const uint2*>(Wb + (size_t)i * 32 * sg.ldW);
        }
    };

    auto sts_chunk = [&](int stage) {
        const uint32_t st = sb + stage * STAGE;
#pragma unroll
        for (int i = 0; i < 4; ++i) {
            sts_v2(st         + stsOff[i], sa[i].x, sa[i].y);
            sts_v2(st + PIECE + stsOff[i], sw[i].x, sw[i].y);
        }
    };

    auto compute = [&](int stage) {
        const uint32_t st = sb + stage * STAGE;
#pragma unroll
        for (int h = 0; h < 2; ++h) {
            const uint32_t hb = h * 32;
            uint32_t Aa[4][4], Bb[2][4];
#pragma unroll
            for (int mf = 0; mf < 4; ++mf)
                LDSM_X4(Aa[mf], st + aOff[mf] + hb);
#pragma unroll
            for (int p = 0; p < 2; ++p)
                LDSM_X4(Bb[p], st + PIECE + bOff[p] + hb);
#pragma unroll
            for (int mf = 0; mf < 4; ++mf)
#pragma unroll
                for (int nf = 0; nf < 4; ++nf) {
                    const int p = nf >> 1, s = nf & 1;
                    mma_f16(acc[mf][nf], Aa[mf], Bb[p][s], Bb[p][s + 2]);
                }
        }
    };

    const int T = NSEG * 16;
    ldg_chunk(0);
    sts_chunk(0);
    __syncthreads();

#pragma unroll 1
    for (int t = 0; t < T; ++t) {
        const bool hasNext = (t + 1 < T);
        if (hasNext) ldg_chunk(t + 1);
        compute(t & 1);
        if (hasNext) {
            sts_chunk((t + 1) & 1);
            __syncthreads();
        }
    }

    // Epilogue
    const float* biasS = reinterpret_cast<const float*>(buf + OFF_BIAS);
    float* Cb = C + (long long)z * strideC;
#pragma unroll
    for (int mf = 0; mf < 4; ++mf) {
#pragma unroll
        for (int nf = 0; nf < 4; ++nf) {
            const int lcol = warp_n * 32 + nf * 8 + (lane & 3) * 2;
            const int r0   = rowBlock + warp_m * 64 + mf * 16 + (lane >> 2);
            const float b0 = biasS[lcol], b1 = biasS[lcol + 1];
            float2 v0 = {acc[mf][nf][0] + b0, acc[mf][nf][1] + b1};
            float2 v1 = {acc[mf][nf][2] + b0, acc[mf][nf][3] + b1};
            *reinterpret_cast<float2*>(Cb + (size_t)r0 * ldC + colBlock + lcol) = v0;
            *reinterpret_cast<float2*>(Cb + (size_t)(r0 + 8) * ldC + colBlock + lcol) = v1;
        }
    }
}

// ---------------------------------------------------------------------------
// LayerNorm + exact GELU: reads fp32 xs, writes fp16 xs_h
// ---------------------------------------------------------------------------
__global__ __launch_bounds__(128)
void ln_gelu_kernel(const float* __restrict__ xs,
                    __half* __restrict__ xs_h,
                    const float* __restrict__ ln_g,
                    const float* __restrict__ ln_b)
{
    using namespace cfg;
    __shared__ float shm[4];
    const long long row = blockIdx.x;
    const int s = (int)(row / B);
    const float* p = xs + row * D;
    const int t = threadIdx.x;

    float4 v = reinterpret_cast<const float4*>(p)[t];

    float sum = v.x + v.y + v.z + v.w;
#pragma unroll
    for (int o = 16; o; o >>= 1) sum += __shfl_xor_sync(0xffffffffu, sum, o);
    if ((t & 31) == 0) shm[t >> 5] = sum;
    __syncthreads();
    const float mean = (shm[0] + shm[1] + shm[2] + shm[3]) * (1.0f / D);
    __syncthreads();

    const float dx = v.x - mean, dy = v.y - mean, dz = v.z - mean, dw = v.w - mean;
    float ss = dx * dx + dy * dy + dz * dz + dw * dw;
#pragma unroll
    for (int o = 16; o; o >>= 1) ss += __shfl_xor_sync(0xffffffffu, ss, o);
    if ((t & 31) == 0) shm[t >> 5] = ss;
    __syncthreads();
    const float var = (shm[0] + shm[1] + shm[2] + shm[3]) * (1.0f / D);
    const float inv = rsqrtf(var + 1e-5f);

    const float4 g4 = reinterpret_cast<const float4*>(ln_g + (long long)s * D)[t];
    const float4 b4 = reinterpret_cast<const float4*>(ln_b + (long long)s * D)[t];

    const float kInvSqrt2 = 0.70710678118654752f;
    float y;
    float4 o4;
    y = dx * inv * g4.x + b4.x; o4.x = 0.5f * y * (1.0f + erff(y * kInvSqrt2));
    y = dy * inv * g4.y + b4.y; o4.y = 0.5f * y * (1.0f + erff(y * kInvSqrt2));
    y = dz * inv * g4.z + b4.z; o4.z = 0.5f * y * (1.0f + erff(y * kInvSqrt2));
    y = dw * inv * g4.w + b4.w; o4.w = 0.5f * y * (1.0f + erff(y * kInvSqrt2));
    reinterpret_cast<uint2*>(xs_h + row * D)[t] = pack_half4(o4);
}

// ---------------------------------------------------------------------------
// LSTM pointwise: gates -> h_new (fp32 + fp16), c_new
// ---------------------------------------------------------------------------
__device__ __forceinline__ float sigmoidf_(float x) { return 1.0f / (1.0f + expf(-x)); }

__global__ __launch_bounds__(256)
void lstm_kernel(const float* __restrict__ gates,
                 const float* __restrict__ c_prev,
                 const float* __restrict__ decays,
                 float* __restrict__ h_new,
                 __half* __restrict__ hnew_h,
                 float* __restrict__ c_new)
{
    using namespace cfg;
    const long long idx = (long long)blockIdx.x * blockDim.x + threadIdx.x;
    const long long total = (long long)S * B * D;
    if (idx >= total) return;

    const int d = (int)(idx % D);
    const long long bs = idx / D;
    const int b = (int)(bs % B);
    const int s = (int)(bs / B);

    const float* g = gates + ((long long)s * B + b) * (4 * D) + d;
    const float ig = g[0];
    const float fg = g[D];
    const float gg = g[2 * D];
    const float og = g[3 * D];

    const float cp  = c_prev[idx];
    const float c_l = sigmoidf_(fg) * cp + sigmoidf_(ig) * tanhf(gg);
    const float h   = sigmoidf_(og) * tanhf(c_l);
    const float dd  = decays[s];

    h_new[idx]  = h;
    hnew_h[idx] = __float2half_rn(h);
    c_new[idx]  = dd * cp + (1.0f - dd) * c_l;
}

// ---------------------------------------------------------------------------
// Attention over S=3: one warp per (b, h) -> fp16 fused
// ---------------------------------------------------------------------------
__global__ __launch_bounds__(256)
void attn_kernel(const float* __restrict__ q,
                 const float* __restrict__ k,
                 const float* __restrict__ v,
                 __half* __restrict__ fused_h)
{
    using namespace cfg;
    const int gwarp = (int)((blockIdx.x * (long long)blockDim.x + threadIdx.x) >> 5);
    const int lane  = threadIdx.x & 31;
    if (gwarp >= B * H) return;
    const int h = gwarp % H;
    const int b = gwarp / H;

    const float* qp = q + (long long)b * D + h * HD;
    const float q0 = qp[lane];
    const float q1 = qp[lane + 32];

    float logits[S];
#pragma unroll
    for (int s = 0; s < S; s++) {
        const float* kp = k + ((long long)s * B + b) * D + h * HD;
        float dot = q0 * kp[lane] + q1 * kp[lane + 32];
#pragma unroll
        for (int o = 16; o; o >>= 1) dot += __shfl_xor_sync(0xffffffffu, dot, o);
        logits[s] = dot * 0.125f;
    }
    float mx = fmaxf(logits[0], fmaxf(logits[1], logits[2]));
    float e0 = expf(logits[0] - mx);
    float e1 = expf(logits[1] - mx);
    float e2 = expf(logits[2] - mx);
    const float rs = 1.0f / (e0 + e1 + e2);
    e0 *= rs; e1 *= rs; e2 *= rs;

    float o0 = 0.0f, o1 = 0.0f;
    const float w[S] = {e0, e1, e2};
#pragma unroll
    for (int s = 0; s < S; s++) {
        const float* vp = v + ((long long)s * B + b) * D + h * HD;
        o0 = fmaf(w[s], vp[lane],      o0);
        o1 = fmaf(w[s], vp[lane + 32], o1);
    }
    __half* fp = fused_h + (long long)b * D + h * HD;
    fp[lane]      = __float2half_rn(o0);
    fp[lane + 32] = __float2half_rn(o1);
}

// ---------------------------------------------------------------------------
// Launcher
// ---------------------------------------------------------------------------
extern "C" void kernel_launch(void* const* d_in, const int* in_sizes, int n_in,
                              void* d_out, int out_size)
{
    using namespace cfg;
    const float* x          = (const float*)d_in[0];
    const float* h_prev     = (const float*)d_in[1];
    const float* c_prev     = (const float*)d_in[2];
    const float* ssm_state  = (const float*)d_in[3];
    const float* Wt         = (const float*)d_in[4];
    const float* bt         = (const float*)d_in[5];
    const float* ln_g       = (const float*)d_in[6];
    const float* ln_b       = (const float*)d_in[7];
    const float* W_ih       = (const float*)d_in[8];
    const float* W_hh       = (const float*)d_in[9];
    const float* b_ih       = (const float*)d_in[10];
    const float* b_hh       = (const float*)d_in[11];
    const float* decays     = (const float*)d_in[12];
    const float* in_proj_w  = (const float*)d_in[13];
    const float* in_proj_b  = (const float*)d_in[14];
    const float* out_proj_w = (const float*)d_in[15];
    const float* out_proj_b = (const float*)d_in[16];
    const float* mix_w      = (const float*)d_in[17];
    const float* mix_b      = (const float*)d_in[18];

    float* out   = (float*)d_out;
    float* h_new = out + N_BD;
    float* c_new = h_new + N_SBD;

    float* scratch = nullptr;
    cudaGetSymbolAddress((void**)&scratch, g_scratch);
    float* xs    = scratch + XS_OFF;
    float* gates = scratch + GATES_OFF;
    float* qf    = scratch + QF_OFF;
    float* kf    = scratch + KF_OFF;
    float* vf    = scratch + VF_OFF;
    __half* x_h     = (__half*)(scratch + XH_OFF);
    __half* hprev_h = (__half*)(scratch + HPREVH_OFF);
    __half* xs_h    = (__half*)(scratch + XSH_OFF);
    __half* hnew_h  = (__half*)(scratch + HNEWH_OFF);
    __half* ssm_h   = (__half*)(scratch + SSMH_OFF);
    __half* fb_h    = (__half*)(scratch + FBH_OFF);
    __half* Wt_h      = (__half*)(scratch + WTH_OFF);
    __half* Wih_h     = (__half*)(scratch + WIHH_OFF);
    __half* Whh_h     = (__half*)(scratch + WHHH_OFF);
    __half* inproj_h  = (__half*)(scratch + INPROJH_OFF);
    __half* outproj_h = (__half*)(scratch + OUTPROJH_OFF);
    __half* mix_h     = (__half*)(scratch + MIXH_OFF);

    cudaFuncSetAttribute(mma_gemm_kernel<1>, cudaFuncAttributeMaxDynamicSharedMemorySize, SMEM_BYTES);
    cudaFuncSetAttribute(mma_gemm_kernel<2>, cudaFuncAttributeMaxDynamicSharedMemorySize, SMEM_BYTES);
    cudaFuncSetAttribute(mma_gemm_kernel<4>, cudaFuncAttributeMaxDynamicSharedMemorySize, SMEM_BYTES);

    const dim3 blk(256);

    // --- launch 0: convert weights + x + h_prev + ssm to fp16 ---
    {
        CvtJobs<9> jobs;
        jobs.j[0] = {(const float4*)Wt,         Wt_h,      (long long)S * D * D / 4};
        jobs.j[1] = {(const float4*)W_ih,       Wih_h,     (long long)S * 4 * D * D / 4};
        jobs.j[2] = {(const float4*)W_hh,       Whh_h,     (long long)S * 4 * D * D / 4};
        jobs.j[3] = {(const float4*)in_proj_w,  inproj_h,  (long long)3 * D * D / 4};
        jobs.j[4] = {(const float4*)out_proj_w, outproj_h, (long long)D * D / 4};
        jobs.j[5] = {(const float4*)mix_w,      mix_h,     (long long)D * 3 * D / 4};
        jobs.j[6] = {(const float4*)x,          x_h,       N_BD / 4};
        jobs.j[7] = {(const float4*)h_prev,     hprev_h,   N_SBD / 4};
        jobs.j[8] = {(const float4*)ssm_state,  ssm_h,     N_BD / 4};
        long long tot = 0;
        for (int i = 0; i < 9; ++i) tot += jobs.j[i].n4;
        cvt_half_kernel<9><<<(int)((tot + 255) / 256), 256>>>(jobs);
    }

    // --- launch 1: xs[s] = x @ Wt[s]^T + bt[s] ---
    {
        SegsH<1> sg;
        sg.s[0] = {x_h, Wt_h, bt, 0, (long long)D * D, D, D, D};
        mma_gemm_kernel<1><<<dim3(D / 128, B / 128, S), blk, SMEM_BYTES>>>(sg, xs, N_BD, D);
    }

    // --- launch 2: LN + GELU -> xs_h ---
    ln_gelu_kernel<<<S * B, 128>>>(xs, xs_h, ln_g, ln_b);

    // --- launch 3: gates = xs@W_ih^T + b_ih + h_prev@W_hh^T + b_hh ---
    {
        SegsH<2> sg;
        sg.s[0] = {xs_h,    Wih_h, b_ih, N_BD, (long long)4 * D * D, 4 * D, D, D};
        sg.s[1] = {hprev_h, Whh_h, b_hh, N_BD, (long long)4 * D * D, 4 * D, D, D};
        mma_gemm_kernel<2><<<dim3(4 * D / 128, B / 128, S), blk, SMEM_BYTES>>>(
            sg, gates, (long long)B * 4 * D, 4 * D);
    }

    // --- launch 4: LSTM pointwise ---
    lstm_kernel<<<(int)((N_SBD + 255) / 256), 256>>>(
        gates, c_prev, decays, h_new, hnew_h, c_new);

    // --- launch 5: k (profiled target) ---
    {
        SegsH<1> sg;
        sg.s[0] = {hnew_h, inproj_h + (long long)D * D, in_proj_b + D, N_BD, 0, 0, D, D};
        mma_gemm_kernel<1><<<dim3(D / 128, B / 128, S), blk, SMEM_BYTES>>>(sg, kf, N_BD, D);
    }
    // --- launch 6: v ---
    {
        SegsH<1> sg;
        sg.s[0] = {hnew_h, inproj_h + 2LL * D * D, in_proj_b + 2 * D, N_BD, 0, 0, D, D};
        mma_gemm_kernel<1><<<dim3(D / 128, B / 128, S), blk, SMEM_BYTES>>>(sg, vf, N_BD, D);
    }
    // --- launch 7: q ---
    {
        SegsH<1> sg;
        sg.s[0] = {ssm_h, inproj_h, in_proj_b, 0, 0, 0, D, D};
        mma_gemm_kernel<1><<<dim3(D / 128, B / 128, 1), blk, SMEM_BYTES>>>(sg, qf, 0, D);
    }

    // --- launch 8: attention -> fb_h ---
    attn_kernel<<<(B * H) / 8, 256>>>(qf, kf, vf, fb_h);

    // --- launch 9: out = fused@out_proj^T + sum_s h_new[s]@mix_w[:,sD:]^T + biases ---
    {
        SegsH<4> sg;
        sg.s[0] = {fb_h,               outproj_h,     out_proj_b, 0, 0, 0, D, D};
        sg.s[1] = {hnew_h,             mix_h,         mix_b,      0, 0, 0, D, S * D};
        sg.s[2] = {hnew_h + N_BD,      mix_h + D,     nullptr,    0, 0, 0, D, S * D};
        sg.s[3] = {hnew_h + 2 * N_BD,  mix_h + 2 * D, nullptr,    0, 0, 0, D, S * D};
        mma_gemm_kernel<4><<<dim3(D / 128, B / 128, 1), blk, SMEM_BYTES>>>(sg, out, 0, D);
    }
}